// round 1
// baseline (speedup 1.0000x reference)
#include <cuda_runtime.h>
#include <cstdint>
#include <math.h>

// ---------------------------------------------------------------------------
// Problem constants
// ---------------------------------------------------------------------------
#define B_ROWS   8192
#define M_EXP    10
#define N_TASK   100
#define F_CONN   10
#define T_OUT    10

// ---------------------------------------------------------------------------
// Scratch (device globals: allocation-free rule workaround)
// ---------------------------------------------------------------------------
__device__ float g_H1[(size_t)M_EXP * B_ROWS * 120];   // expert layer-1 out
__device__ float g_H2[(size_t)M_EXP * B_ROWS * 84];    // expert layer-2 out
__device__ float g_EO[(size_t)M_EXP * B_ROWS * 10];    // expert out [M,B,F]
__device__ float g_G [(size_t)N_TASK * B_ROWS * 10];   // gates_out  [N,B,F]
__device__ float g_T1[(size_t)N_TASK * B_ROWS * 120];  // task layer-1 out
__device__ float g_T2[(size_t)N_TASK * B_ROWS * 84];   // task layer-2 out

// ---------------------------------------------------------------------------
// Packed f32x2 helpers (Blackwell FFMA2: 2x fp32 FMA rate vs scalar FFMA)
// ---------------------------------------------------------------------------
__device__ __forceinline__ void fma2(unsigned long long& d,
                                     unsigned long long a,
                                     unsigned long long b) {
    asm("fma.rn.f32x2 %0, %1, %2, %0;" : "+l"(d) : "l"(a), "l"(b));
}
__device__ __forceinline__ unsigned long long dup2(float x) {
    unsigned long long r;
    unsigned int xi = __float_as_uint(x);
    asm("mov.b64 %0, {%1, %1};" : "=l"(r) : "r"(xi));
    return r;
}
__device__ __forceinline__ void unpack2(unsigned long long v, float& lo, float& hi) {
    unsigned int a, b;
    asm("mov.b64 {%0, %1}, %2;" : "=r"(a), "=r"(b) : "l"(v));
    lo = __uint_as_float(a);
    hi = __uint_as_float(b);
}

// ---------------------------------------------------------------------------
// Generic batched GEMM + bias (+ optional relu):
//   C[z][r][c] = act( sum_k A[z][r][k] * W[z][k][c] + bias[z][c] )
// Rows fixed at 8192 (BM=128 * gridDim.y=64). Cols c < N (guarded), N <= 16*TN.
// Register tile: 8 rows x TN cols per thread, f32x2 packed over row pairs.
// ---------------------------------------------------------------------------
template<int TN, bool RELU>
__global__ __launch_bounds__(256, 2)
void sgemm_bias_kernel(const float* __restrict__ A, long long aBatchStride,
                       const float* __restrict__ W,     // [batch][K][N]
                       const float* __restrict__ bias,  // [batch][N]
                       float* __restrict__ C, long long cBatchStride,
                       int K, int N)
{
    constexpr int BM = 128, BK = 8, BN = 16 * TN;
    __shared__ float As[BK][BM];   // transposed: [k][row]
    __shared__ float Ws[BK][BN];   // [k][col]

    const int batch = blockIdx.z;
    const int r0 = blockIdx.y * BM;
    const float* Ab = A + (long long)batch * aBatchStride;
    const float* Wb = W + (long long)batch * K * N;
    float* Cb = C + (long long)batch * cBatchStride;

    const int t  = threadIdx.x;
    const int ty = t >> 4;   // 0..15 -> row group of 8
    const int tx = t & 15;   // 0..15 -> col group of TN

    unsigned long long acc[4][TN];
    #pragma unroll
    for (int rp = 0; rp < 4; rp++)
        #pragma unroll
        for (int j = 0; j < TN; j++)
            acc[rp][j] = 0ULL;   // bit pattern of {0.f, 0.f}

    const bool kvec_ok = ((K & 3) == 0);

    for (int k0 = 0; k0 < K; k0 += BK) {
        // ---- load A tile: BM x BK (1024 floats, 4 per thread) ----
        {
            int flat = t * 4;
            int r  = flat >> 3;   // /BK
            int kk = flat & 7;
            const float* src = Ab + (long long)(r0 + r) * K + (k0 + kk);
            float v0, v1, v2, v3;
            if (kvec_ok && (k0 + kk + 4 <= K)) {
                float4 f = *reinterpret_cast<const float4*>(src);
                v0 = f.x; v1 = f.y; v2 = f.z; v3 = f.w;
            } else {
                v0 = (k0 + kk + 0 < K) ? src[0] : 0.f;
                v1 = (k0 + kk + 1 < K) ? src[1] : 0.f;
                v2 = (k0 + kk + 2 < K) ? src[2] : 0.f;
                v3 = (k0 + kk + 3 < K) ? src[3] : 0.f;
            }
            As[kk + 0][r] = v0;
            As[kk + 1][r] = v1;
            As[kk + 2][r] = v2;
            As[kk + 3][r] = v3;
        }
        // ---- load W tile: BK x BN (zero-fill out-of-range k or c) ----
        #pragma unroll
        for (int i = 0; i < (BK * BN) / 256; i++) {
            int flat = i * 256 + t;
            int kk = flat / BN;
            int c  = flat % BN;
            float v = ((k0 + kk) < K && c < N) ? Wb[(long long)(k0 + kk) * N + c] : 0.f;
            Ws[kk][c] = v;
        }
        __syncthreads();

        // ---- compute: 8 k-steps, 8 rows x TN cols each ----
        #pragma unroll
        for (int kk = 0; kk < BK; kk++) {
            unsigned long long ap[4];
            const unsigned long long* arow =
                reinterpret_cast<const unsigned long long*>(&As[kk][ty * 8]);
            #pragma unroll
            for (int rp = 0; rp < 4; rp++) ap[rp] = arow[rp];

            unsigned long long wd[TN];
            #pragma unroll
            for (int j = 0; j < TN; j++) wd[j] = dup2(Ws[kk][tx * TN + j]);

            #pragma unroll
            for (int rp = 0; rp < 4; rp++)
                #pragma unroll
                for (int j = 0; j < TN; j++)
                    fma2(acc[rp][j], ap[rp], wd[j]);
        }
        __syncthreads();
    }

    // ---- epilogue: bias (+relu), store ----
    #pragma unroll
    for (int j = 0; j < TN; j++) {
        int c = tx * TN + j;
        if (c < N) {
            float bv = bias[(long long)batch * N + c];
            #pragma unroll
            for (int rp = 0; rp < 4; rp++) {
                float lo, hi;
                unpack2(acc[rp][j], lo, hi);
                lo += bv; hi += bv;
                if (RELU) { lo = fmaxf(lo, 0.f); hi = fmaxf(hi, 0.f); }
                long long r = r0 + ty * 8 + rp * 2;
                Cb[r * N + c]       = lo;
                Cb[(r + 1) * N + c] = hi;
            }
        }
    }
}

// ---------------------------------------------------------------------------
// Gating combine: gates_out[n][b][f] = sum_m (gate_w[m][n]*mask[m][n]) * EO[m][b][f]
// ---------------------------------------------------------------------------
__global__ void gate_kernel(const float* __restrict__ eo,
                            const float* __restrict__ gw,
                            const int*   __restrict__ gm,
                            float* __restrict__ gout)
{
    int idx = blockIdx.x * blockDim.x + threadIdx.x;
    const int total = N_TASK * B_ROWS * F_CONN;   // 8,192,000
    if (idx >= total) return;
    int f = idx % F_CONN;
    int b = (idx / F_CONN) % B_ROWS;
    int n = idx / (F_CONN * B_ROWS);
    float acc = 0.f;
    #pragma unroll
    for (int m = 0; m < M_EXP; m++) {
        float w = gw[m * N_TASK + n] * (float)gm[m * N_TASK + n];
        acc = fmaf(w, eo[((long long)m * B_ROWS + b) * F_CONN + f], acc);
    }
    gout[idx] = acc;
}

// ---------------------------------------------------------------------------
// logits_loss[n] = sum_m log_sigmoid(gate_logits[m][n])
// ---------------------------------------------------------------------------
__global__ void logits_kernel(const float* __restrict__ gl, float* __restrict__ out)
{
    int n = blockIdx.x * blockDim.x + threadIdx.x;
    if (n >= N_TASK) return;
    float acc = 0.f;
    #pragma unroll
    for (int m = 0; m < M_EXP; m++) {
        float v = gl[m * N_TASK + n];
        // stable log(sigmoid(v))
        float ls = (v > 0.f) ? (-log1pf(expf(-v))) : (v - log1pf(expf(v)));
        acc += ls;
    }
    out[n] = acc;
}

// ---------------------------------------------------------------------------
// kernel_launch: graph-capturable, allocation-free
// Inputs (metadata order):
//  0:x 1:task 2:eW1 3:eb1 4:eW2 5:eb2 6:eW3 7:eb3
//  8:gate_w 9:gate_logits 10:gate_mask(int32)
//  11:tW1 12:tb1 13:tW2 14:tb2 15:tW3 16:tb3
// Output: task_out [100,8192,10] then logits_loss [100]
// ---------------------------------------------------------------------------
extern "C" void kernel_launch(void* const* d_in, const int* in_sizes, int n_in,
                              void* d_out, int out_size)
{
    const float* x   = (const float*)d_in[0];
    const float* eW1 = (const float*)d_in[2];
    const float* eb1 = (const float*)d_in[3];
    const float* eW2 = (const float*)d_in[4];
    const float* eb2 = (const float*)d_in[5];
    const float* eW3 = (const float*)d_in[6];
    const float* eb3 = (const float*)d_in[7];
    const float* gw  = (const float*)d_in[8];
    const float* gl  = (const float*)d_in[9];
    const int*   gm  = (const int*)  d_in[10];
    const float* tW1 = (const float*)d_in[11];
    const float* tb1 = (const float*)d_in[12];
    const float* tW2 = (const float*)d_in[13];
    const float* tb2 = (const float*)d_in[14];
    const float* tW3 = (const float*)d_in[15];
    const float* tb3 = (const float*)d_in[16];
    float* out = (float*)d_out;

    float *H1, *H2, *EO, *G, *T1b, *T2b;
    cudaGetSymbolAddress((void**)&H1,  g_H1);
    cudaGetSymbolAddress((void**)&H2,  g_H2);
    cudaGetSymbolAddress((void**)&EO,  g_EO);
    cudaGetSymbolAddress((void**)&G,   g_G);
    cudaGetSymbolAddress((void**)&T1b, g_T1);
    cudaGetSymbolAddress((void**)&T2b, g_T2);

    const dim3 blk(256);
    const int rowTiles = B_ROWS / 128;   // 64

    // E1: [B,4096] @ eW1[m][4096][120] -> H1[m][B][120], relu  (x shared: aBatchStride=0)
    sgemm_bias_kernel<8, true><<<dim3(1, rowTiles, M_EXP), blk>>>(
        x, 0LL, eW1, eb1, H1, (long long)B_ROWS * 120, 4096, 120);

    // E2: H1 @ eW2[m][120][84] -> H2, relu
    sgemm_bias_kernel<8, true><<<dim3(1, rowTiles, M_EXP), blk>>>(
        H1, (long long)B_ROWS * 120, eW2, eb2, H2, (long long)B_ROWS * 84, 120, 84);

    // E3: H2 @ eW3[m][84][10] -> EO (no relu)
    sgemm_bias_kernel<2, false><<<dim3(1, rowTiles, M_EXP), blk>>>(
        H2, (long long)B_ROWS * 84, eW3, eb3, EO, (long long)B_ROWS * 10, 84, 10);

    // gating combine -> G[n][B][10]
    {
        int total = N_TASK * B_ROWS * F_CONN;
        gate_kernel<<<(total + 255) / 256, 256>>>(EO, gw, gm, G);
    }

    // T1: G @ tW1[n][10][120] -> T1b, relu
    sgemm_bias_kernel<8, true><<<dim3(1, rowTiles, N_TASK), blk>>>(
        G, (long long)B_ROWS * 10, tW1, tb1, T1b, (long long)B_ROWS * 120, 10, 120);

    // T2: T1b @ tW2[n][120][84] -> T2b, relu
    sgemm_bias_kernel<8, true><<<dim3(1, rowTiles, N_TASK), blk>>>(
        T1b, (long long)B_ROWS * 120, tW2, tb2, T2b, (long long)B_ROWS * 84, 120, 84);

    // T3: T2b @ tW3[n][84][10] -> out (no relu), [n][b][t]
    sgemm_bias_kernel<2, false><<<dim3(1, rowTiles, N_TASK), blk>>>(
        T2b, (long long)B_ROWS * 84, tW3, tb3, out, (long long)B_ROWS * 10, 84, 10);

    // logits_loss -> out tail
    logits_kernel<<<1, 128>>>(gl, out + (long long)N_TASK * B_ROWS * T_OUT);
}

// round 4
// speedup vs baseline: 1.5242x; 1.5242x over previous
#include <cuda_runtime.h>
#include <cuda_bf16.h>
#include <cstdint>
#include <math.h>

// ---------------------------------------------------------------------------
// Problem constants
// ---------------------------------------------------------------------------
#define B_ROWS   8192
#define M_EXP    10
#define N_TASK   100
#define F_CONN   10
#define T_OUT    10
#define K_IN     4096
#define H1_DIM   120

// ---------------------------------------------------------------------------
// Scratch (device globals: allocation-free rule workaround)
// ---------------------------------------------------------------------------
__device__ float g_H1[(size_t)M_EXP * B_ROWS * 120];   // expert layer-1 out
__device__ float g_H2[(size_t)M_EXP * B_ROWS * 84];    // expert layer-2 out
__device__ float g_EO[(size_t)M_EXP * B_ROWS * 10];    // expert out [M,B,F]
__device__ float g_G [(size_t)N_TASK * B_ROWS * 10];   // gates_out  [N,B,F]
__device__ float g_T1[(size_t)N_TASK * B_ROWS * 120];  // task layer-1 out
__device__ float g_T2[(size_t)N_TASK * B_ROWS * 84];   // task layer-2 out

// bf16 split buffers for the E1 tensor path
__device__ __nv_bfloat16 g_xh[(size_t)B_ROWS * K_IN];          // x hi  [b][k]
__device__ __nv_bfloat16 g_xl[(size_t)B_ROWS * K_IN];          // x lo
__device__ __nv_bfloat16 g_wh[(size_t)M_EXP * H1_DIM * K_IN];  // eW1^T hi [m][n][k]
__device__ __nv_bfloat16 g_wl[(size_t)M_EXP * H1_DIM * K_IN];  // eW1^T lo

// ---------------------------------------------------------------------------
// Packed f32x2 helpers (Blackwell FFMA2) for the SIMT GEMM path
// ---------------------------------------------------------------------------
__device__ __forceinline__ void fma2(unsigned long long& d,
                                     unsigned long long a,
                                     unsigned long long b) {
    asm("fma.rn.f32x2 %0, %1, %2, %0;" : "+l"(d) : "l"(a), "l"(b));
}
__device__ __forceinline__ unsigned long long dup2(float x) {
    unsigned long long r;
    unsigned int xi = __float_as_uint(x);
    asm("mov.b64 %0, {%1, %1};" : "=l"(r) : "r"(xi));
    return r;
}
__device__ __forceinline__ void unpack2(unsigned long long v, float& lo, float& hi) {
    unsigned int a, b;
    asm("mov.b64 {%0, %1}, %2;" : "=r"(a), "=r"(b) : "l"(v));
    lo = __uint_as_float(a);
    hi = __uint_as_float(b);
}

// ---------------------------------------------------------------------------
// PTX helpers (sm_80-era features only: legal at virtual arch compute_103)
// ---------------------------------------------------------------------------
__device__ __forceinline__ uint32_t smem_u32(const void* p) {
    uint32_t a;
    asm("{ .reg .u64 t; cvta.to.shared.u64 t, %1; cvt.u32.u64 %0, t; }"
        : "=r"(a) : "l"(p));
    return a;
}
__device__ __forceinline__ void cp16(uint32_t s, const void* g) {
    asm volatile("cp.async.cg.shared.global [%0], [%1], 16;" :: "r"(s), "l"(g));
}
__device__ __forceinline__ void cp_commit() {
    asm volatile("cp.async.commit_group;" ::: "memory");
}
template<int N> __device__ __forceinline__ void cp_wait() {
    asm volatile("cp.async.wait_group %0;" :: "n"(N) : "memory");
}
__device__ __forceinline__ void ldsm_x4(uint32_t& r0, uint32_t& r1,
                                        uint32_t& r2, uint32_t& r3, uint32_t a) {
    asm volatile("ldmatrix.sync.aligned.m8n8.x4.shared.b16 {%0,%1,%2,%3}, [%4];"
                 : "=r"(r0), "=r"(r1), "=r"(r2), "=r"(r3) : "r"(a));
}
__device__ __forceinline__ void mma_bf16(float& c0, float& c1, float& c2, float& c3,
                                         uint32_t a0, uint32_t a1, uint32_t a2, uint32_t a3,
                                         uint32_t b0, uint32_t b1) {
    asm volatile("mma.sync.aligned.m16n8k16.row.col.f32.bf16.bf16.f32 "
                 "{%0,%1,%2,%3},{%4,%5,%6,%7},{%8,%9},{%0,%1,%2,%3};"
                 : "+f"(c0), "+f"(c1), "+f"(c2), "+f"(c3)
                 : "r"(a0), "r"(a1), "r"(a2), "r"(a3), "r"(b0), "r"(b1));
}

// ---------------------------------------------------------------------------
// Conversion kernels: fp32 -> (bf16 hi, bf16 lo)
// ---------------------------------------------------------------------------
__global__ void convert_x_kernel(const float* __restrict__ x,
                                 __nv_bfloat16* __restrict__ xh,
                                 __nv_bfloat16* __restrict__ xl)
{
    size_t i = (size_t)blockIdx.x * blockDim.x + threadIdx.x;
    const size_t total = (size_t)B_ROWS * K_IN;
    if (i >= total) return;
    float v = x[i];
    __nv_bfloat16 h = __float2bfloat16(v);
    float rem = v - __bfloat162float(h);
    xh[i] = h;
    xl[i] = __float2bfloat16(rem);
}

// eW1 [m][k][n] -> transposed hi/lo [m][n][k]
__global__ void convert_w_kernel(const float* __restrict__ w,
                                 __nv_bfloat16* __restrict__ wh,
                                 __nv_bfloat16* __restrict__ wl)
{
    size_t i = (size_t)blockIdx.x * blockDim.x + threadIdx.x;
    const size_t total = (size_t)M_EXP * K_IN * H1_DIM;
    if (i >= total) return;
    size_t m = i / ((size_t)K_IN * H1_DIM);
    size_t rem = i % ((size_t)K_IN * H1_DIM);
    size_t k = rem / H1_DIM;
    size_t n = rem % H1_DIM;
    float v = w[i];
    __nv_bfloat16 h = __float2bfloat16(v);
    float r2 = v - __bfloat162float(h);
    size_t o = (m * H1_DIM + n) * K_IN + k;
    wh[o] = h;
    wl[o] = __float2bfloat16(r2);
}

// ---------------------------------------------------------------------------
// E1 HMMA kernel: H1[m][r][120] = relu(x[r,:] @ eW1[m] + eb1[m])
// bf16-split 3-pass mma.sync.m16n8k16, BM=128, BN=128(pad of 120), BK=32,
// 256 threads = 8 warps (4m x 2n), warp tile 32x64.
// SMEM rows padded to 80B stride -> conflict-free ldmatrix, no swizzle.
// grid = (M_EXP, B_ROWS/128)
// ---------------------------------------------------------------------------
#define E1_BK        32
#define E1_NC        (K_IN / E1_BK)     // 128 iters
#define E1_RSTRIDE   80                 // bytes per smem row (40 bf16)
#define E1_MAT       10240              // 128 rows * 80B
#define E1_AH        0
#define E1_AL        10240
#define E1_BH        20480
#define E1_BL        30720
#define E1_STAGE     40960
#define E1_SMEM      (2 * E1_STAGE)     // 81920 bytes

static __device__ __forceinline__ void e1_load_stage(
    uint32_t sbase, int k0,
    const __nv_bfloat16* __restrict__ xh_t, const __nv_bfloat16* __restrict__ xl_t,
    const __nv_bfloat16* __restrict__ wh_m, const __nv_bfloat16* __restrict__ wl_m,
    int t)
{
    // A: 128 rows x 4 16B-chunks (=32 bf16) per matrix
    #pragma unroll
    for (int i = 0; i < 2; i++) {
        int u = t + i * 256;          // 0..511
        int r = u >> 2, c4 = u & 3;
        uint32_t dst = sbase + r * E1_RSTRIDE + c4 * 16;
        const __nv_bfloat16* s1 = xh_t + (size_t)r * K_IN + k0 + c4 * 8;
        const __nv_bfloat16* s2 = xl_t + (size_t)r * K_IN + k0 + c4 * 8;
        cp16(dst + E1_AH, s1);
        cp16(dst + E1_AL, s2);
    }
    // B: 120 rows x 4 chunks per matrix
    #pragma unroll
    for (int i = 0; i < 2; i++) {
        int u = t + i * 256;
        if (u < 480) {
            int r = u >> 2, c4 = u & 3;
            uint32_t dst = sbase + r * E1_RSTRIDE + c4 * 16;
            cp16(dst + E1_BH, wh_m + (size_t)r * K_IN + k0 + c4 * 8);
            cp16(dst + E1_BL, wl_m + (size_t)r * K_IN + k0 + c4 * 8);
        }
    }
}

__global__ __launch_bounds__(256)
void e1_mma_kernel(const __nv_bfloat16* __restrict__ xh,
                   const __nv_bfloat16* __restrict__ xl,
                   const __nv_bfloat16* __restrict__ wh,
                   const __nv_bfloat16* __restrict__ wl,
                   const float* __restrict__ eb1,
                   float* __restrict__ H1)
{
    extern __shared__ char smem[];
    const uint32_t sb = smem_u32(smem);
    const int t    = threadIdx.x;
    const int lane = t & 31;
    const int wid  = t >> 5;
    const int wm   = wid >> 1;   // 0..3 (m-dim)
    const int wn   = wid & 1;    // 0..1 (n-dim)

    const int m  = blockIdx.x;
    const int r0 = blockIdx.y * 128;

    const __nv_bfloat16* xh_t = xh + (size_t)r0 * K_IN;
    const __nv_bfloat16* xl_t = xl + (size_t)r0 * K_IN;
    const __nv_bfloat16* wh_m = wh + (size_t)m * H1_DIM * K_IN;
    const __nv_bfloat16* wl_m = wl + (size_t)m * H1_DIM * K_IN;

    // zero the B pad rows (120..127) in both stages, both matrices
    for (int u = t; u < 8 * 20 * 2 * 2; u += 256) {
        int w32  = u % 160;                // 8 rows * 20 u32/row
        int mat  = (u / 160) & 1;          // 0=BH,1=BL
        int stg  = (u / 320);              // stage
        int r    = 120 + (w32 / 20);
        int c    = w32 % 20;
        *reinterpret_cast<uint32_t*>(smem + stg * E1_STAGE +
            (mat ? E1_BL : E1_BH) + r * E1_RSTRIDE + c * 4) = 0u;
    }

    // accumulators: [mt 2][nt 8][4]
    float acc[2][8][4];
    #pragma unroll
    for (int i = 0; i < 2; i++)
        #pragma unroll
        for (int j = 0; j < 8; j++)
            #pragma unroll
            for (int q = 0; q < 4; q++)
                acc[i][j][q] = 0.f;

    // per-lane ldmatrix base offsets (within a matrix, stage 0, kstep 0)
    const uint32_t a_base = (uint32_t)((wm * 32 + (lane & 15)) * E1_RSTRIDE +
                                       (lane >> 4) * 16);
    const uint32_t b_base = (uint32_t)((wn * 64 + (lane & 15)) * E1_RSTRIDE +
                                       (lane >> 4) * 16);

    // prologue
    e1_load_stage(sb, 0, xh_t, xl_t, wh_m, wl_m, t);
    cp_commit();

    for (int c = 0; c < E1_NC; c++) {
        const int s = c & 1;
        if (c + 1 < E1_NC) {
            e1_load_stage(sb + (s ^ 1) * E1_STAGE, (c + 1) * E1_BK,
                          xh_t, xl_t, wh_m, wl_m, t);
            cp_commit();
            cp_wait<1>();
        } else {
            cp_wait<0>();
        }
        __syncthreads();

        const uint32_t stg = sb + s * E1_STAGE;
        #pragma unroll
        for (int ks = 0; ks < 2; ks++) {
            const uint32_t ko = ks * 32;   // 16 bf16 = 32B per kstep
            // A fragments (hi, lo) for 2 m-tiles
            uint32_t ah[2][4], al[2][4];
            #pragma unroll
            for (int mt = 0; mt < 2; mt++) {
                uint32_t ad = stg + a_base + mt * (16 * E1_RSTRIDE) + ko;
                ldsm_x4(ah[mt][0], ah[mt][1], ah[mt][2], ah[mt][3], ad + E1_AH);
                ldsm_x4(al[mt][0], al[mt][1], al[mt][2], al[mt][3], ad + E1_AL);
            }
            // B fragments (hi, lo): 4 groups of 16 n-rows (2 n-tiles each)
            // ldmatrix x4 register meaning within group g:
            //   reg0 = (n0-7,  k0-7), reg1 = (n8-15, k0-7),
            //   reg2 = (n0-7, k8-15), reg3 = (n8-15, k8-15)
            uint32_t bh[4][4], bl[4][4];
            #pragma unroll
            for (int g = 0; g < 4; g++) {
                uint32_t bd = stg + b_base + g * (16 * E1_RSTRIDE) + ko;
                ldsm_x4(bh[g][0], bh[g][1], bh[g][2], bh[g][3], bd + E1_BH);
                ldsm_x4(bl[g][0], bl[g][1], bl[g][2], bl[g][3], bd + E1_BL);
            }
            // 3-pass MMA.  B operand pairing: {(n,k0-7), (same n,k8-15)}
            //   nt even -> regs {0, 2};  nt odd -> regs {1, 3}
            #pragma unroll
            for (int mt = 0; mt < 2; mt++) {
                #pragma unroll
                for (int nt = 0; nt < 8; nt++) {
                    const int g = nt >> 1, p = (nt & 1);
                    float* cc = acc[mt][nt];
                    mma_bf16(cc[0], cc[1], cc[2], cc[3],
                             ah[mt][0], ah[mt][1], ah[mt][2], ah[mt][3],
                             bh[g][p], bh[g][p + 2]);
                    mma_bf16(cc[0], cc[1], cc[2], cc[3],
                             ah[mt][0], ah[mt][1], ah[mt][2], ah[mt][3],
                             bl[g][p], bl[g][p + 2]);
                    mma_bf16(cc[0], cc[1], cc[2], cc[3],
                             al[mt][0], al[mt][1], al[mt][2], al[mt][3],
                             bh[g][p], bh[g][p + 2]);
                }
            }
        }
        __syncthreads();
    }

    // epilogue: bias + relu, direct fp32 stores
    const float* bias = eb1 + (size_t)m * H1_DIM;
    const int row_base = r0 + wm * 32 + (lane >> 2);
    const int col_base = wn * 64 + (lane & 3) * 2;
    #pragma unroll
    for (int mt = 0; mt < 2; mt++) {
        #pragma unroll
        for (int half = 0; half < 2; half++) {
            const int r = row_base + mt * 16 + half * 8;
            float* dst = H1 + ((size_t)m * B_ROWS + r) * H1_DIM;
            #pragma unroll
            for (int nt = 0; nt < 8; nt++) {
                const int ccol = col_base + nt * 8;
                if (ccol < H1_DIM) {
                    float2 v;
                    v.x = fmaxf(acc[mt][nt][half * 2 + 0] + bias[ccol], 0.f);
                    v.y = fmaxf(acc[mt][nt][half * 2 + 1] + bias[ccol + 1], 0.f);
                    *reinterpret_cast<float2*>(dst + ccol) = v;
                }
            }
        }
    }
}

// ---------------------------------------------------------------------------
// Generic batched GEMM + bias (+ optional relu)  [SIMT / FFMA2 path]
// ---------------------------------------------------------------------------
template<int TN, bool RELU>
__global__ __launch_bounds__(256, 2)
void sgemm_bias_kernel(const float* __restrict__ A, long long aBatchStride,
                       const float* __restrict__ W,
                       const float* __restrict__ bias,
                       float* __restrict__ C, long long cBatchStride,
                       int K, int N)
{
    constexpr int BM = 128, BK = 8, BN = 16 * TN;
    __shared__ float As[BK][BM];
    __shared__ float Ws[BK][BN];

    const int batch = blockIdx.z;
    const int r0 = blockIdx.y * BM;
    const float* Ab = A + (long long)batch * aBatchStride;
    const float* Wb = W + (long long)batch * K * N;
    float* Cb = C + (long long)batch * cBatchStride;

    const int t  = threadIdx.x;
    const int ty = t >> 4;
    const int tx = t & 15;

    unsigned long long acc[4][TN];
    #pragma unroll
    for (int rp = 0; rp < 4; rp++)
        #pragma unroll
        for (int j = 0; j < TN; j++)
            acc[rp][j] = 0ULL;

    const bool kvec_ok = ((K & 3) == 0);

    for (int k0 = 0; k0 < K; k0 += BK) {
        {
            int flat = t * 4;
            int r  = flat >> 3;
            int kk = flat & 7;
            const float* src = Ab + (long long)(r0 + r) * K + (k0 + kk);
            float v0, v1, v2, v3;
            if (kvec_ok && (k0 + kk + 4 <= K)) {
                float4 f = *reinterpret_cast<const float4*>(src);
                v0 = f.x; v1 = f.y; v2 = f.z; v3 = f.w;
            } else {
                v0 = (k0 + kk + 0 < K) ? src[0] : 0.f;
                v1 = (k0 + kk + 1 < K) ? src[1] : 0.f;
                v2 = (k0 + kk + 2 < K) ? src[2] : 0.f;
                v3 = (k0 + kk + 3 < K) ? src[3] : 0.f;
            }
            As[kk + 0][r] = v0;
            As[kk + 1][r] = v1;
            As[kk + 2][r] = v2;
            As[kk + 3][r] = v3;
        }
        #pragma unroll
        for (int i = 0; i < (BK * BN) / 256; i++) {
            int flat = i * 256 + t;
            int kk = flat / BN;
            int c  = flat % BN;
            float v = ((k0 + kk) < K && c < N) ? Wb[(long long)(k0 + kk) * N + c] : 0.f;
            Ws[kk][c] = v;
        }
        __syncthreads();

        #pragma unroll
        for (int kk = 0; kk < BK; kk++) {
            unsigned long long ap[4];
            const unsigned long long* arow =
                reinterpret_cast<const unsigned long long*>(&As[kk][ty * 8]);
            #pragma unroll
            for (int rp = 0; rp < 4; rp++) ap[rp] = arow[rp];

            unsigned long long wd[TN];
            #pragma unroll
            for (int j = 0; j < TN; j++) wd[j] = dup2(Ws[kk][tx * TN + j]);

            #pragma unroll
            for (int rp = 0; rp < 4; rp++)
                #pragma unroll
                for (int j = 0; j < TN; j++)
                    fma2(acc[rp][j], ap[rp], wd[j]);
        }
        __syncthreads();
    }

    #pragma unroll
    for (int j = 0; j < TN; j++) {
        int c = tx * TN + j;
        if (c < N) {
            float bv = bias[(long long)batch * N + c];
            #pragma unroll
            for (int rp = 0; rp < 4; rp++) {
                float lo, hi;
                unpack2(acc[rp][j], lo, hi);
                lo += bv; hi += bv;
                if (RELU) { lo = fmaxf(lo, 0.f); hi = fmaxf(hi, 0.f); }
                long long r = r0 + ty * 8 + rp * 2;
                Cb[r * N + c]       = lo;
                Cb[(r + 1) * N + c] = hi;
            }
        }
    }
}

// ---------------------------------------------------------------------------
// Gating combine
// ---------------------------------------------------------------------------
__global__ void gate_kernel(const float* __restrict__ eo,
                            const float* __restrict__ gw,
                            const int*   __restrict__ gm,
                            float* __restrict__ gout)
{
    int idx = blockIdx.x * blockDim.x + threadIdx.x;
    const int total = N_TASK * B_ROWS * F_CONN;
    if (idx >= total) return;
    int f = idx % F_CONN;
    int b = (idx / F_CONN) % B_ROWS;
    int n = idx / (F_CONN * B_ROWS);
    float acc = 0.f;
    #pragma unroll
    for (int m = 0; m < M_EXP; m++) {
        float w = gw[m * N_TASK + n] * (float)gm[m * N_TASK + n];
        acc = fmaf(w, eo[((long long)m * B_ROWS + b) * F_CONN + f], acc);
    }
    gout[idx] = acc;
}

__global__ void logits_kernel(const float* __restrict__ gl, float* __restrict__ out)
{
    int n = blockIdx.x * blockDim.x + threadIdx.x;
    if (n >= N_TASK) return;
    float acc = 0.f;
    #pragma unroll
    for (int m = 0; m < M_EXP; m++) {
        float v = gl[m * N_TASK + n];
        float ls = (v > 0.f) ? (-log1pf(expf(-v))) : (v - log1pf(expf(v)));
        acc += ls;
    }
    out[n] = acc;
}

// ---------------------------------------------------------------------------
// kernel_launch
// ---------------------------------------------------------------------------
extern "C" void kernel_launch(void* const* d_in, const int* in_sizes, int n_in,
                              void* d_out, int out_size)
{
    const float* x   = (const float*)d_in[0];
    const float* eW1 = (const float*)d_in[2];
    const float* eb1 = (const float*)d_in[3];
    const float* eW2 = (const float*)d_in[4];
    const float* eb2 = (const float*)d_in[5];
    const float* eW3 = (const float*)d_in[6];
    const float* eb3 = (const float*)d_in[7];
    const float* gw  = (const float*)d_in[8];
    const float* gl  = (const float*)d_in[9];
    const int*   gm  = (const int*)  d_in[10];
    const float* tW1 = (const float*)d_in[11];
    const float* tb1 = (const float*)d_in[12];
    const float* tW2 = (const float*)d_in[13];
    const float* tb2 = (const float*)d_in[14];
    const float* tW3 = (const float*)d_in[15];
    const float* tb3 = (const float*)d_in[16];
    float* out = (float*)d_out;

    float *H1, *H2, *EO, *G, *T1b, *T2b;
    __nv_bfloat16 *xh, *xl, *wh, *wl;
    cudaGetSymbolAddress((void**)&H1,  g_H1);
    cudaGetSymbolAddress((void**)&H2,  g_H2);
    cudaGetSymbolAddress((void**)&EO,  g_EO);
    cudaGetSymbolAddress((void**)&G,   g_G);
    cudaGetSymbolAddress((void**)&T1b, g_T1);
    cudaGetSymbolAddress((void**)&T2b, g_T2);
    cudaGetSymbolAddress((void**)&xh,  g_xh);
    cudaGetSymbolAddress((void**)&xl,  g_xl);
    cudaGetSymbolAddress((void**)&wh,  g_wh);
    cudaGetSymbolAddress((void**)&wl,  g_wl);

    cudaFuncSetAttribute(e1_mma_kernel,
                         cudaFuncAttributeMaxDynamicSharedMemorySize, E1_SMEM);

    const dim3 blk(256);
    const int rowTiles = B_ROWS / 128;   // 64

    // ---- E1 (HMMA mma.sync, bf16-split 3-pass) ----
    {
        size_t nx = (size_t)B_ROWS * K_IN;
        convert_x_kernel<<<(unsigned)((nx + 255) / 256), 256>>>(x, xh, xl);
        size_t nw = (size_t)M_EXP * K_IN * H1_DIM;
        convert_w_kernel<<<(unsigned)((nw + 255) / 256), 256>>>(eW1, wh, wl);
        e1_mma_kernel<<<dim3(M_EXP, rowTiles), blk, E1_SMEM>>>(
            xh, xl, wh, wl, eb1, H1);
    }

    // E2: H1 @ eW2[m][120][84] -> H2, relu
    sgemm_bias_kernel<8, true><<<dim3(1, rowTiles, M_EXP), blk>>>(
        H1, (long long)B_ROWS * 120, eW2, eb2, H2, (long long)B_ROWS * 84, 120, 84);

    // E3: H2 @ eW3[m][84][10] -> EO
    sgemm_bias_kernel<2, false><<<dim3(1, rowTiles, M_EXP), blk>>>(
        H2, (long long)B_ROWS * 84, eW3, eb3, EO, (long long)B_ROWS * 10, 84, 10);

    // gating combine -> G[n][B][10]
    {
        int total = N_TASK * B_ROWS * F_CONN;
        gate_kernel<<<(total + 255) / 256, 256>>>(EO, gw, gm, G);
    }

    // T1: G @ tW1[n][10][120] -> T1b, relu
    sgemm_bias_kernel<8, true><<<dim3(1, rowTiles, N_TASK), blk>>>(
        G, (long long)B_ROWS * 10, tW1, tb1, T1b, (long long)B_ROWS * 120, 10, 120);

    // T2: T1b @ tW2[n][120][84] -> T2b, relu
    sgemm_bias_kernel<8, true><<<dim3(1, rowTiles, N_TASK), blk>>>(
        T1b, (long long)B_ROWS * 120, tW2, tb2, T2b, (long long)B_ROWS * 84, 120, 84);

    // T3: T2b @ tW3[n][84][10] -> out
    sgemm_bias_kernel<2, false><<<dim3(1, rowTiles, N_TASK), blk>>>(
        T2b, (long long)B_ROWS * 84, tW3, tb3, out, (long long)B_ROWS * 10, 84, 10);

    // logits_loss -> out tail
    logits_kernel<<<1, 128>>>(gl, out + (long long)N_TASK * B_ROWS * T_OUT);
}

// round 5
// speedup vs baseline: 1.9520x; 1.2807x over previous
#include <cuda_runtime.h>
#include <cuda_bf16.h>
#include <cstdint>
#include <math.h>

// ---------------------------------------------------------------------------
// Problem constants
// ---------------------------------------------------------------------------
#define B_ROWS   8192
#define M_EXP    10
#define N_TASK   100
#define F_CONN   10
#define T_OUT    10
#define K_IN     4096
#define H1_DIM   120

// ---------------------------------------------------------------------------
// Scratch (device globals: allocation-free rule workaround)
// ---------------------------------------------------------------------------
__device__ float g_H1[(size_t)M_EXP * B_ROWS * 120];   // expert layer-1 out
__device__ float g_H2[(size_t)M_EXP * B_ROWS * 84];    // expert layer-2 out
__device__ float g_EO[(size_t)M_EXP * B_ROWS * 10];    // expert out [M,B,F]
__device__ float g_G [(size_t)N_TASK * B_ROWS * 10];   // gates_out  [N,B,F]
__device__ float g_T1[(size_t)N_TASK * B_ROWS * 120];  // task layer-1 out
__device__ float g_T2[(size_t)N_TASK * B_ROWS * 84];   // task layer-2 out

// bf16 split buffers for the E1 tensor path
__device__ __nv_bfloat16 g_xh[(size_t)B_ROWS * K_IN];          // x hi  [b][k]
__device__ __nv_bfloat16 g_xl[(size_t)B_ROWS * K_IN];          // x lo
__device__ __nv_bfloat16 g_wh[(size_t)M_EXP * H1_DIM * K_IN];  // eW1^T hi [m][n][k]
__device__ __nv_bfloat16 g_wl[(size_t)M_EXP * H1_DIM * K_IN];  // eW1^T lo

// bf16 split transposed+padded weights for E2/T2 HMMA path: [batch][96][128]
__device__ __nv_bfloat16 g_w2h[(size_t)M_EXP * 96 * 128];
__device__ __nv_bfloat16 g_w2l[(size_t)M_EXP * 96 * 128];
__device__ __nv_bfloat16 g_tw2h[(size_t)N_TASK * 96 * 128];
__device__ __nv_bfloat16 g_tw2l[(size_t)N_TASK * 96 * 128];

// ---------------------------------------------------------------------------
// Packed f32x2 helpers (Blackwell FFMA2) for the SIMT GEMM path
// ---------------------------------------------------------------------------
__device__ __forceinline__ void fma2(unsigned long long& d,
                                     unsigned long long a,
                                     unsigned long long b) {
    asm("fma.rn.f32x2 %0, %1, %2, %0;" : "+l"(d) : "l"(a), "l"(b));
}
__device__ __forceinline__ unsigned long long dup2(float x) {
    unsigned long long r;
    unsigned int xi = __float_as_uint(x);
    asm("mov.b64 %0, {%1, %1};" : "=l"(r) : "r"(xi));
    return r;
}
__device__ __forceinline__ void unpack2(unsigned long long v, float& lo, float& hi) {
    unsigned int a, b;
    asm("mov.b64 {%0, %1}, %2;" : "=r"(a), "=r"(b) : "l"(v));
    lo = __uint_as_float(a);
    hi = __uint_as_float(b);
}

// ---------------------------------------------------------------------------
// PTX helpers (sm_80-era features only: legal at virtual arch compute_103)
// ---------------------------------------------------------------------------
__device__ __forceinline__ uint32_t smem_u32(const void* p) {
    uint32_t a;
    asm("{ .reg .u64 t; cvta.to.shared.u64 t, %1; cvt.u32.u64 %0, t; }"
        : "=r"(a) : "l"(p));
    return a;
}
__device__ __forceinline__ void cp16(uint32_t s, const void* g) {
    asm volatile("cp.async.cg.shared.global [%0], [%1], 16;" :: "r"(s), "l"(g));
}
__device__ __forceinline__ void cp_commit() {
    asm volatile("cp.async.commit_group;" ::: "memory");
}
template<int N> __device__ __forceinline__ void cp_wait() {
    asm volatile("cp.async.wait_group %0;" :: "n"(N) : "memory");
}
__device__ __forceinline__ void ldsm_x4(uint32_t& r0, uint32_t& r1,
                                        uint32_t& r2, uint32_t& r3, uint32_t a) {
    asm volatile("ldmatrix.sync.aligned.m8n8.x4.shared.b16 {%0,%1,%2,%3}, [%4];"
                 : "=r"(r0), "=r"(r1), "=r"(r2), "=r"(r3) : "r"(a));
}
__device__ __forceinline__ void mma_bf16(float& c0, float& c1, float& c2, float& c3,
                                         uint32_t a0, uint32_t a1, uint32_t a2, uint32_t a3,
                                         uint32_t b0, uint32_t b1) {
    asm volatile("mma.sync.aligned.m16n8k16.row.col.f32.bf16.bf16.f32 "
                 "{%0,%1,%2,%3},{%4,%5,%6,%7},{%8,%9},{%0,%1,%2,%3};"
                 : "+f"(c0), "+f"(c1), "+f"(c2), "+f"(c3)
                 : "r"(a0), "r"(a1), "r"(a2), "r"(a3), "r"(b0), "r"(b1));
}

// ---------------------------------------------------------------------------
// Conversion kernels: fp32 -> (bf16 hi, bf16 lo)
// ---------------------------------------------------------------------------
__global__ void convert_x_kernel(const float* __restrict__ x,
                                 __nv_bfloat16* __restrict__ xh,
                                 __nv_bfloat16* __restrict__ xl)
{
    size_t i = (size_t)blockIdx.x * blockDim.x + threadIdx.x;
    const size_t total = (size_t)B_ROWS * K_IN;
    if (i >= total) return;
    float v = x[i];
    __nv_bfloat16 h = __float2bfloat16(v);
    float rem = v - __bfloat162float(h);
    xh[i] = h;
    xl[i] = __float2bfloat16(rem);
}

// eW1 [m][k][n] -> transposed hi/lo [m][n][k]
__global__ void convert_w_kernel(const float* __restrict__ w,
                                 __nv_bfloat16* __restrict__ wh,
                                 __nv_bfloat16* __restrict__ wl)
{
    size_t i = (size_t)blockIdx.x * blockDim.x + threadIdx.x;
    const size_t total = (size_t)M_EXP * K_IN * H1_DIM;
    if (i >= total) return;
    size_t m = i / ((size_t)K_IN * H1_DIM);
    size_t rem = i % ((size_t)K_IN * H1_DIM);
    size_t k = rem / H1_DIM;
    size_t n = rem % H1_DIM;
    float v = w[i];
    __nv_bfloat16 h = __float2bfloat16(v);
    float r2 = v - __bfloat162float(h);
    size_t o = (m * H1_DIM + n) * K_IN + k;
    wh[o] = h;
    wl[o] = __float2bfloat16(r2);
}

// w [b][Kreal][Nreal] -> wh/wl [b][96][128] transposed + zero padded
__global__ void convert_w2_kernel(const float* __restrict__ w, int batchN,
                                  int Kreal, int Nreal,
                                  __nv_bfloat16* __restrict__ wh,
                                  __nv_bfloat16* __restrict__ wl)
{
    size_t i = (size_t)blockIdx.x * blockDim.x + threadIdx.x;
    size_t total = (size_t)batchN * 96 * 128;
    if (i >= total) return;
    int k = (int)(i % 128);
    int n = (int)((i / 128) % 96);
    int b = (int)(i / (128 * 96));
    float v = (k < Kreal && n < Nreal) ? w[((size_t)b * Kreal + k) * Nreal + n] : 0.f;
    __nv_bfloat16 h = __float2bfloat16(v);
    wh[i] = h;
    wl[i] = __float2bfloat16(v - __bfloat162float(h));
}

// ---------------------------------------------------------------------------
// E1 HMMA kernel: H1[m][r][120] = relu(x[r,:] @ eW1[m] + eb1[m])
// bf16-split 3-pass mma.sync.m16n8k16, BM=128, BN=128(pad of 120), BK=32,
// 256 threads = 8 warps (4m x 2n), warp tile 32x64.
// SMEM rows padded to 80B stride -> conflict-free ldmatrix, no swizzle.
// grid = (M_EXP, B_ROWS/128)
// ---------------------------------------------------------------------------
#define E1_BK        32
#define E1_NC        (K_IN / E1_BK)     // 128 iters
#define E1_RSTRIDE   80                 // bytes per smem row (40 bf16)
#define E1_MAT       10240              // 128 rows * 80B
#define E1_AH        0
#define E1_AL        10240
#define E1_BH        20480
#define E1_BL        30720
#define E1_STAGE     40960
#define E1_SMEM      (2 * E1_STAGE)     // 81920 bytes

static __device__ __forceinline__ void e1_load_stage(
    uint32_t sbase, int k0,
    const __nv_bfloat16* __restrict__ xh_t, const __nv_bfloat16* __restrict__ xl_t,
    const __nv_bfloat16* __restrict__ wh_m, const __nv_bfloat16* __restrict__ wl_m,
    int t)
{
    // A: 128 rows x 4 16B-chunks (=32 bf16) per matrix
    #pragma unroll
    for (int i = 0; i < 2; i++) {
        int u = t + i * 256;          // 0..511
        int r = u >> 2, c4 = u & 3;
        uint32_t dst = sbase + r * E1_RSTRIDE + c4 * 16;
        const __nv_bfloat16* s1 = xh_t + (size_t)r * K_IN + k0 + c4 * 8;
        const __nv_bfloat16* s2 = xl_t + (size_t)r * K_IN + k0 + c4 * 8;
        cp16(dst + E1_AH, s1);
        cp16(dst + E1_AL, s2);
    }
    // B: 120 rows x 4 chunks per matrix
    #pragma unroll
    for (int i = 0; i < 2; i++) {
        int u = t + i * 256;
        if (u < 480) {
            int r = u >> 2, c4 = u & 3;
            uint32_t dst = sbase + r * E1_RSTRIDE + c4 * 16;
            cp16(dst + E1_BH, wh_m + (size_t)r * K_IN + k0 + c4 * 8);
            cp16(dst + E1_BL, wl_m + (size_t)r * K_IN + k0 + c4 * 8);
        }
    }
}

__global__ __launch_bounds__(256)
void e1_mma_kernel(const __nv_bfloat16* __restrict__ xh,
                   const __nv_bfloat16* __restrict__ xl,
                   const __nv_bfloat16* __restrict__ wh,
                   const __nv_bfloat16* __restrict__ wl,
                   const float* __restrict__ eb1,
                   float* __restrict__ H1)
{
    extern __shared__ char smem[];
    const uint32_t sb = smem_u32(smem);
    const int t    = threadIdx.x;
    const int lane = t & 31;
    const int wid  = t >> 5;
    const int wm   = wid >> 1;   // 0..3 (m-dim)
    const int wn   = wid & 1;    // 0..1 (n-dim)

    const int m  = blockIdx.x;
    const int r0 = blockIdx.y * 128;

    const __nv_bfloat16* xh_t = xh + (size_t)r0 * K_IN;
    const __nv_bfloat16* xl_t = xl + (size_t)r0 * K_IN;
    const __nv_bfloat16* wh_m = wh + (size_t)m * H1_DIM * K_IN;
    const __nv_bfloat16* wl_m = wl + (size_t)m * H1_DIM * K_IN;

    // zero the B pad rows (120..127) in both stages, both matrices
    for (int u = t; u < 8 * 20 * 2 * 2; u += 256) {
        int w32  = u % 160;                // 8 rows * 20 u32/row
        int mat  = (u / 160) & 1;          // 0=BH,1=BL
        int stg  = (u / 320);              // stage
        int r    = 120 + (w32 / 20);
        int c    = w32 % 20;
        *reinterpret_cast<uint32_t*>(smem + stg * E1_STAGE +
            (mat ? E1_BL : E1_BH) + r * E1_RSTRIDE + c * 4) = 0u;
    }

    // accumulators: [mt 2][nt 8][4]
    float acc[2][8][4];
    #pragma unroll
    for (int i = 0; i < 2; i++)
        #pragma unroll
        for (int j = 0; j < 8; j++)
            #pragma unroll
            for (int q = 0; q < 4; q++)
                acc[i][j][q] = 0.f;

    // per-lane ldmatrix base offsets (within a matrix, stage 0, kstep 0)
    const uint32_t a_base = (uint32_t)((wm * 32 + (lane & 15)) * E1_RSTRIDE +
                                       (lane >> 4) * 16);
    const uint32_t b_base = (uint32_t)((wn * 64 + (lane & 15)) * E1_RSTRIDE +
                                       (lane >> 4) * 16);

    // prologue
    e1_load_stage(sb, 0, xh_t, xl_t, wh_m, wl_m, t);
    cp_commit();

    for (int c = 0; c < E1_NC; c++) {
        const int s = c & 1;
        if (c + 1 < E1_NC) {
            e1_load_stage(sb + (s ^ 1) * E1_STAGE, (c + 1) * E1_BK,
                          xh_t, xl_t, wh_m, wl_m, t);
            cp_commit();
            cp_wait<1>();
        } else {
            cp_wait<0>();
        }
        __syncthreads();

        const uint32_t stg = sb + s * E1_STAGE;
        #pragma unroll
        for (int ks = 0; ks < 2; ks++) {
            const uint32_t ko = ks * 32;   // 16 bf16 = 32B per kstep
            // A fragments (hi, lo) for 2 m-tiles
            uint32_t ah[2][4], al[2][4];
            #pragma unroll
            for (int mt = 0; mt < 2; mt++) {
                uint32_t ad = stg + a_base + mt * (16 * E1_RSTRIDE) + ko;
                ldsm_x4(ah[mt][0], ah[mt][1], ah[mt][2], ah[mt][3], ad + E1_AH);
                ldsm_x4(al[mt][0], al[mt][1], al[mt][2], al[mt][3], ad + E1_AL);
            }
            // B fragments (hi, lo): reg0=(n0-7,k0-7) reg1=(n8-15,k0-7)
            //                       reg2=(n0-7,k8-15) reg3=(n8-15,k8-15)
            uint32_t bh[4][4], bl[4][4];
            #pragma unroll
            for (int g = 0; g < 4; g++) {
                uint32_t bd = stg + b_base + g * (16 * E1_RSTRIDE) + ko;
                ldsm_x4(bh[g][0], bh[g][1], bh[g][2], bh[g][3], bd + E1_BH);
                ldsm_x4(bl[g][0], bl[g][1], bl[g][2], bl[g][3], bd + E1_BL);
            }
            // 3-pass MMA.  B operand pairing: {(n,k0-7), (same n,k8-15)}
            #pragma unroll
            for (int mt = 0; mt < 2; mt++) {
                #pragma unroll
                for (int nt = 0; nt < 8; nt++) {
                    const int g = nt >> 1, p = (nt & 1);
                    float* cc = acc[mt][nt];
                    mma_bf16(cc[0], cc[1], cc[2], cc[3],
                             ah[mt][0], ah[mt][1], ah[mt][2], ah[mt][3],
                             bh[g][p], bh[g][p + 2]);
                    mma_bf16(cc[0], cc[1], cc[2], cc[3],
                             ah[mt][0], ah[mt][1], ah[mt][2], ah[mt][3],
                             bl[g][p], bl[g][p + 2]);
                    mma_bf16(cc[0], cc[1], cc[2], cc[3],
                             al[mt][0], al[mt][1], al[mt][2], al[mt][3],
                             bh[g][p], bh[g][p + 2]);
                }
            }
        }
        __syncthreads();
    }

    // epilogue: bias + relu, direct fp32 stores
    const float* bias = eb1 + (size_t)m * H1_DIM;
    const int row_base = r0 + wm * 32 + (lane >> 2);
    const int col_base = wn * 64 + (lane & 3) * 2;
    #pragma unroll
    for (int mt = 0; mt < 2; mt++) {
        #pragma unroll
        for (int half = 0; half < 2; half++) {
            const int r = row_base + mt * 16 + half * 8;
            float* dst = H1 + ((size_t)m * B_ROWS + r) * H1_DIM;
            #pragma unroll
            for (int nt = 0; nt < 8; nt++) {
                const int ccol = col_base + nt * 8;
                if (ccol < H1_DIM) {
                    float2 v;
                    v.x = fmaxf(acc[mt][nt][half * 2 + 0] + bias[ccol], 0.f);
                    v.y = fmaxf(acc[mt][nt][half * 2 + 1] + bias[ccol + 1], 0.f);
                    *reinterpret_cast<float2*>(dst + ccol) = v;
                }
            }
        }
    }
}

// ---------------------------------------------------------------------------
// E2/T2 HMMA kernel: C[b][r][84] = relu(A[b][r][0:120] @ W[b] + bias[b])
// A fp32 (lda=120) converted to bf16 hi/lo in-kernel.  W pre-converted
// transposed padded [b][96][128] hi/lo.  K padded to 128 (4 iters of 32).
// BM=128, BN=96, 8 warps (4m x 2n), warp tile 32x48.
// grid = (batch, 64)
// ---------------------------------------------------------------------------
#define G2_KP      128
#define G2_KR      120
#define G2_NP      96
#define G2_NR      84
#define G2_RS      80                   // smem row stride bytes
#define G2_RAW     0                    // 128 rows * 128B fp32 = 16384
#define G2_AH      16384                // 128*80 = 10240
#define G2_AL      26624
#define G2_BH      36864                // 96*80 = 7680
#define G2_BL      44544
#define G2_SMEM    52224

__global__ __launch_bounds__(256)
void mma_gemm_k120_kernel(const float* __restrict__ A, long long aBatch,
                          const __nv_bfloat16* __restrict__ Wh,
                          const __nv_bfloat16* __restrict__ Wl,
                          const float* __restrict__ bias,
                          float* __restrict__ C, long long cBatch)
{
    extern __shared__ char smem[];
    const uint32_t sb = smem_u32(smem);
    const int t    = threadIdx.x;
    const int lane = t & 31;
    const int wid  = t >> 5;
    const int wm   = wid >> 1;   // 0..3
    const int wn   = wid & 1;    // 0..1

    const int batch = blockIdx.x;
    const int r0    = blockIdx.y * 128;

    const float* Ab = A + (long long)batch * aBatch + (size_t)r0 * G2_KR;
    const __nv_bfloat16* WhB = Wh + (size_t)batch * G2_NP * G2_KP;
    const __nv_bfloat16* WlB = Wl + (size_t)batch * G2_NP * G2_KP;

    float acc[2][6][4];
    #pragma unroll
    for (int i = 0; i < 2; i++)
        #pragma unroll
        for (int j = 0; j < 6; j++)
            #pragma unroll
            for (int q = 0; q < 4; q++)
                acc[i][j][q] = 0.f;

    const uint32_t a_base = (uint32_t)((wm * 32 + (lane & 15)) * G2_RS +
                                       (lane >> 4) * 16);
    const uint32_t b_base = (uint32_t)((wn * 48 + (lane & 15)) * G2_RS +
                                       (lane >> 4) * 16);

    for (int it = 0; it < 4; it++) {
        const int k0 = it * 32;
        // ---- load raw A fp32: 128 rows x 8 chunks of 16B ----
        #pragma unroll
        for (int i = 0; i < 4; i++) {
            int u = t + i * 256;          // 0..1023
            int r = u >> 3, c4 = u & 7;
            int k = k0 + c4 * 4;
            if (k < G2_KR) {
                cp16(sb + G2_RAW + r * 128 + c4 * 16,
                     Ab + (size_t)r * G2_KR + k);
            } else {
                *reinterpret_cast<uint4*>(smem + G2_RAW + r * 128 + c4 * 16) =
                    make_uint4(0u, 0u, 0u, 0u);
            }
        }
        // ---- load B hi/lo: 96 rows x 4 chunks x 2 mats ----
        #pragma unroll
        for (int i = 0; i < 3; i++) {
            int u = t + i * 256;          // 0..767
            int mat = u / 384;
            int v = u % 384;
            int rr = v >> 2, c4 = v & 3;
            uint32_t dst = sb + (mat ? G2_BL : G2_BH) + rr * G2_RS + c4 * 16;
            const __nv_bfloat16* src =
                (mat ? WlB : WhB) + (size_t)rr * G2_KP + k0 + c4 * 8;
            cp16(dst, src);
        }
        cp_commit();
        cp_wait<0>();
        __syncthreads();

        // ---- convert raw fp32 -> Ah/Al (bf16) ----
        #pragma unroll
        for (int j = 0; j < 8; j++) {
            int e = t + j * 256;          // 0..2047 col-pairs
            int r = e >> 4, cp2 = e & 15;
            float2 v = *reinterpret_cast<const float2*>(
                smem + G2_RAW + r * 128 + cp2 * 8);
            __nv_bfloat16 h0 = __float2bfloat16(v.x);
            __nv_bfloat16 h1 = __float2bfloat16(v.y);
            float l0 = v.x - __bfloat162float(h0);
            float l1 = v.y - __bfloat162float(h1);
            __nv_bfloat162 hh; hh.x = h0; hh.y = h1;
            __nv_bfloat162 ll; ll.x = __float2bfloat16(l0); ll.y = __float2bfloat16(l1);
            *reinterpret_cast<__nv_bfloat162*>(smem + G2_AH + r * G2_RS + cp2 * 4) = hh;
            *reinterpret_cast<__nv_bfloat162*>(smem + G2_AL + r * G2_RS + cp2 * 4) = ll;
        }
        __syncthreads();

        // ---- MMA ----
        #pragma unroll
        for (int ks = 0; ks < 2; ks++) {
            const uint32_t ko = ks * 32;
            uint32_t ah[2][4], al[2][4];
            #pragma unroll
            for (int mt = 0; mt < 2; mt++) {
                uint32_t ad = sb + a_base + mt * (16 * G2_RS) + ko;
                ldsm_x4(ah[mt][0], ah[mt][1], ah[mt][2], ah[mt][3], ad + G2_AH);
                ldsm_x4(al[mt][0], al[mt][1], al[mt][2], al[mt][3], ad + G2_AL);
            }
            uint32_t bh[3][4], bl[3][4];
            #pragma unroll
            for (int g = 0; g < 3; g++) {
                uint32_t bd = sb + b_base + g * (16 * G2_RS) + ko;
                ldsm_x4(bh[g][0], bh[g][1], bh[g][2], bh[g][3], bd + G2_BH);
                ldsm_x4(bl[g][0], bl[g][1], bl[g][2], bl[g][3], bd + G2_BL);
            }
            #pragma unroll
            for (int mt = 0; mt < 2; mt++) {
                #pragma unroll
                for (int nt = 0; nt < 6; nt++) {
                    const int g = nt >> 1, p = (nt & 1);
                    float* cc = acc[mt][nt];
                    mma_bf16(cc[0], cc[1], cc[2], cc[3],
                             ah[mt][0], ah[mt][1], ah[mt][2], ah[mt][3],
                             bh[g][p], bh[g][p + 2]);
                    mma_bf16(cc[0], cc[1], cc[2], cc[3],
                             ah[mt][0], ah[mt][1], ah[mt][2], ah[mt][3],
                             bl[g][p], bl[g][p + 2]);
                    mma_bf16(cc[0], cc[1], cc[2], cc[3],
                             al[mt][0], al[mt][1], al[mt][2], al[mt][3],
                             bh[g][p], bh[g][p + 2]);
                }
            }
        }
        __syncthreads();
    }

    // ---- epilogue: bias + relu ----
    const float* bias_b = bias + (size_t)batch * G2_NR;
    const int row_base = r0 + wm * 32 + (lane >> 2);
    const int col_base = wn * 48 + (lane & 3) * 2;
    #pragma unroll
    for (int mt = 0; mt < 2; mt++) {
        #pragma unroll
        for (int half = 0; half < 2; half++) {
            const int r = row_base + mt * 16 + half * 8;
            float* dst = C + (long long)batch * cBatch + (size_t)r * G2_NR;
            #pragma unroll
            for (int nt = 0; nt < 6; nt++) {
                const int ccol = col_base + nt * 8;
                if (ccol < G2_NR) {
                    float2 v;
                    v.x = fmaxf(acc[mt][nt][half * 2 + 0] + bias_b[ccol], 0.f);
                    v.y = fmaxf(acc[mt][nt][half * 2 + 1] + bias_b[ccol + 1], 0.f);
                    *reinterpret_cast<float2*>(dst + ccol) = v;
                }
            }
        }
    }
}

// ---------------------------------------------------------------------------
// Generic batched GEMM + bias (+ optional relu)  [SIMT / FFMA2 path]
// ---------------------------------------------------------------------------
template<int TN, bool RELU>
__global__ __launch_bounds__(256, 2)
void sgemm_bias_kernel(const float* __restrict__ A, long long aBatchStride,
                       const float* __restrict__ W,
                       const float* __restrict__ bias,
                       float* __restrict__ C, long long cBatchStride,
                       int K, int N)
{
    constexpr int BM = 128, BK = 8, BN = 16 * TN;
    __shared__ float As[BK][BM];
    __shared__ float Ws[BK][BN];

    const int batch = blockIdx.z;
    const int r0 = blockIdx.y * BM;
    const float* Ab = A + (long long)batch * aBatchStride;
    const float* Wb = W + (long long)batch * K * N;
    float* Cb = C + (long long)batch * cBatchStride;

    const int t  = threadIdx.x;
    const int ty = t >> 4;
    const int tx = t & 15;

    unsigned long long acc[4][TN];
    #pragma unroll
    for (int rp = 0; rp < 4; rp++)
        #pragma unroll
        for (int j = 0; j < TN; j++)
            acc[rp][j] = 0ULL;

    const bool kvec_ok = ((K & 3) == 0);

    for (int k0 = 0; k0 < K; k0 += BK) {
        {
            int flat = t * 4;
            int r  = flat >> 3;
            int kk = flat & 7;
            const float* src = Ab + (long long)(r0 + r) * K + (k0 + kk);
            float v0, v1, v2, v3;
            if (kvec_ok && (k0 + kk + 4 <= K)) {
                float4 f = *reinterpret_cast<const float4*>(src);
                v0 = f.x; v1 = f.y; v2 = f.z; v3 = f.w;
            } else {
                v0 = (k0 + kk + 0 < K) ? src[0] : 0.f;
                v1 = (k0 + kk + 1 < K) ? src[1] : 0.f;
                v2 = (k0 + kk + 2 < K) ? src[2] : 0.f;
                v3 = (k0 + kk + 3 < K) ? src[3] : 0.f;
            }
            As[kk + 0][r] = v0;
            As[kk + 1][r] = v1;
            As[kk + 2][r] = v2;
            As[kk + 3][r] = v3;
        }
        #pragma unroll
        for (int i = 0; i < (BK * BN) / 256; i++) {
            int flat = i * 256 + t;
            int kk = flat / BN;
            int c  = flat % BN;
            float v = ((k0 + kk) < K && c < N) ? Wb[(long long)(k0 + kk) * N + c] : 0.f;
            Ws[kk][c] = v;
        }
        __syncthreads();

        #pragma unroll
        for (int kk = 0; kk < BK; kk++) {
            unsigned long long ap[4];
            const unsigned long long* arow =
                reinterpret_cast<const unsigned long long*>(&As[kk][ty * 8]);
            #pragma unroll
            for (int rp = 0; rp < 4; rp++) ap[rp] = arow[rp];

            unsigned long long wd[TN];
            #pragma unroll
            for (int j = 0; j < TN; j++) wd[j] = dup2(Ws[kk][tx * TN + j]);

            #pragma unroll
            for (int rp = 0; rp < 4; rp++)
                #pragma unroll
                for (int j = 0; j < TN; j++)
                    fma2(acc[rp][j], ap[rp], wd[j]);
        }
        __syncthreads();
    }

    #pragma unroll
    for (int j = 0; j < TN; j++) {
        int c = tx * TN + j;
        if (c < N) {
            float bv = bias[(long long)batch * N + c];
            #pragma unroll
            for (int rp = 0; rp < 4; rp++) {
                float lo, hi;
                unpack2(acc[rp][j], lo, hi);
                lo += bv; hi += bv;
                if (RELU) { lo = fmaxf(lo, 0.f); hi = fmaxf(hi, 0.f); }
                long long r = r0 + ty * 8 + rp * 2;
                Cb[r * N + c]       = lo;
                Cb[(r + 1) * N + c] = hi;
            }
        }
    }
}

// ---------------------------------------------------------------------------
// Gating combine
// ---------------------------------------------------------------------------
__global__ void gate_kernel(const float* __restrict__ eo,
                            const float* __restrict__ gw,
                            const int*   __restrict__ gm,
                            float* __restrict__ gout)
{
    int idx = blockIdx.x * blockDim.x + threadIdx.x;
    const int total = N_TASK * B_ROWS * F_CONN;
    if (idx >= total) return;
    int f = idx % F_CONN;
    int b = (idx / F_CONN) % B_ROWS;
    int n = idx / (F_CONN * B_ROWS);
    float acc = 0.f;
    #pragma unroll
    for (int m = 0; m < M_EXP; m++) {
        float w = gw[m * N_TASK + n] * (float)gm[m * N_TASK + n];
        acc = fmaf(w, eo[((long long)m * B_ROWS + b) * F_CONN + f], acc);
    }
    gout[idx] = acc;
}

__global__ void logits_kernel(const float* __restrict__ gl, float* __restrict__ out)
{
    int n = blockIdx.x * blockDim.x + threadIdx.x;
    if (n >= N_TASK) return;
    float acc = 0.f;
    #pragma unroll
    for (int m = 0; m < M_EXP; m++) {
        float v = gl[m * N_TASK + n];
        float ls = (v > 0.f) ? (-log1pf(expf(-v))) : (v - log1pf(expf(v)));
        acc += ls;
    }
    out[n] = acc;
}

// ---------------------------------------------------------------------------
// kernel_launch
// ---------------------------------------------------------------------------
extern "C" void kernel_launch(void* const* d_in, const int* in_sizes, int n_in,
                              void* d_out, int out_size)
{
    const float* x   = (const float*)d_in[0];
    const float* eW1 = (const float*)d_in[2];
    const float* eb1 = (const float*)d_in[3];
    const float* eW2 = (const float*)d_in[4];
    const float* eb2 = (const float*)d_in[5];
    const float* eW3 = (const float*)d_in[6];
    const float* eb3 = (const float*)d_in[7];
    const float* gw  = (const float*)d_in[8];
    const float* gl  = (const float*)d_in[9];
    const int*   gm  = (const int*)  d_in[10];
    const float* tW1 = (const float*)d_in[11];
    const float* tb1 = (const float*)d_in[12];
    const float* tW2 = (const float*)d_in[13];
    const float* tb2 = (const float*)d_in[14];
    const float* tW3 = (const float*)d_in[15];
    const float* tb3 = (const float*)d_in[16];
    float* out = (float*)d_out;

    float *H1, *H2, *EO, *G, *T1b, *T2b;
    __nv_bfloat16 *xh, *xl, *wh, *wl, *w2h, *w2l, *tw2h, *tw2l;
    cudaGetSymbolAddress((void**)&H1,  g_H1);
    cudaGetSymbolAddress((void**)&H2,  g_H2);
    cudaGetSymbolAddress((void**)&EO,  g_EO);
    cudaGetSymbolAddress((void**)&G,   g_G);
    cudaGetSymbolAddress((void**)&T1b, g_T1);
    cudaGetSymbolAddress((void**)&T2b, g_T2);
    cudaGetSymbolAddress((void**)&xh,  g_xh);
    cudaGetSymbolAddress((void**)&xl,  g_xl);
    cudaGetSymbolAddress((void**)&wh,  g_wh);
    cudaGetSymbolAddress((void**)&wl,  g_wl);
    cudaGetSymbolAddress((void**)&w2h, g_w2h);
    cudaGetSymbolAddress((void**)&w2l, g_w2l);
    cudaGetSymbolAddress((void**)&tw2h, g_tw2h);
    cudaGetSymbolAddress((void**)&tw2l, g_tw2l);

    cudaFuncSetAttribute(e1_mma_kernel,
                         cudaFuncAttributeMaxDynamicSharedMemorySize, E1_SMEM);
    cudaFuncSetAttribute(mma_gemm_k120_kernel,
                         cudaFuncAttributeMaxDynamicSharedMemorySize, G2_SMEM);

    const dim3 blk(256);
    const int rowTiles = B_ROWS / 128;   // 64

    // ---- weight conversions (small) ----
    {
        size_t nx = (size_t)B_ROWS * K_IN;
        convert_x_kernel<<<(unsigned)((nx + 255) / 256), 256>>>(x, xh, xl);
        size_t nw = (size_t)M_EXP * K_IN * H1_DIM;
        convert_w_kernel<<<(unsigned)((nw + 255) / 256), 256>>>(eW1, wh, wl);
        size_t n2 = (size_t)M_EXP * 96 * 128;
        convert_w2_kernel<<<(unsigned)((n2 + 255) / 256), 256>>>(
            eW2, M_EXP, 120, 84, w2h, w2l);
        size_t n3 = (size_t)N_TASK * 96 * 128;
        convert_w2_kernel<<<(unsigned)((n3 + 255) / 256), 256>>>(
            tW2, N_TASK, 120, 84, tw2h, tw2l);
    }

    // ---- E1 (HMMA, bf16-split 3-pass) ----
    e1_mma_kernel<<<dim3(M_EXP, rowTiles), blk, E1_SMEM>>>(
        xh, xl, wh, wl, eb1, H1);

    // ---- E2 (HMMA): H1 @ eW2 -> H2, relu ----
    mma_gemm_k120_kernel<<<dim3(M_EXP, rowTiles), blk, G2_SMEM>>>(
        H1, (long long)B_ROWS * 120, w2h, w2l, eb2,
        H2, (long long)B_ROWS * 84);

    // E3: H2 @ eW3[m][84][10] -> EO  (SIMT)
    sgemm_bias_kernel<2, false><<<dim3(1, rowTiles, M_EXP), blk>>>(
        H2, (long long)B_ROWS * 84, eW3, eb3, EO, (long long)B_ROWS * 10, 84, 10);

    // gating combine -> G[n][B][10]
    {
        int total = N_TASK * B_ROWS * F_CONN;
        gate_kernel<<<(total + 255) / 256, 256>>>(EO, gw, gm, G);
    }

    // T1: G @ tW1[n][10][120] -> T1b, relu  (SIMT, K=10)
    sgemm_bias_kernel<8, true><<<dim3(1, rowTiles, N_TASK), blk>>>(
        G, (long long)B_ROWS * 10, tW1, tb1, T1b, (long long)B_ROWS * 120, 10, 120);

    // ---- T2 (HMMA): T1 @ tW2 -> T2b, relu ----
    mma_gemm_k120_kernel<<<dim3(N_TASK, rowTiles), blk, G2_SMEM>>>(
        T1b, (long long)B_ROWS * 120, tw2h, tw2l, tb2,
        T2b, (long long)B_ROWS * 84);

    // T3: T2b @ tW3[n][84][10] -> out  (SIMT)
    sgemm_bias_kernel<2, false><<<dim3(1, rowTiles, N_TASK), blk>>>(
        T2b, (long long)B_ROWS * 84, tW3, tb3, out, (long long)B_ROWS * 10, 84, 10);

    // logits_loss -> out tail
    logits_kernel<<<1, 128>>>(gl, out + (long long)N_TASK * B_ROWS * T_OUT);
}

// round 6
// speedup vs baseline: 2.3959x; 1.2274x over previous
#include <cuda_runtime.h>
#include <cuda_bf16.h>
#include <cstdint>
#include <math.h>

// ---------------------------------------------------------------------------
// Problem constants
// ---------------------------------------------------------------------------
#define B_ROWS   8192
#define M_EXP    10
#define N_TASK   100
#define F_CONN   10
#define T_OUT    10
#define K_IN     4096
#define H1_DIM   120

// ---------------------------------------------------------------------------
// Scratch (device globals: allocation-free rule workaround)
// ---------------------------------------------------------------------------
__device__ float g_H1[(size_t)M_EXP * B_ROWS * 120];   // expert layer-1 out
__device__ float g_EO[(size_t)M_EXP * B_ROWS * 10];    // expert out [M,B,F]
__device__ float g_T1[(size_t)N_TASK * B_ROWS * 120];  // task layer-1 out

// bf16 split buffers for the E1 tensor path
__device__ __nv_bfloat16 g_xh[(size_t)B_ROWS * K_IN];          // x hi  [b][k]
__device__ __nv_bfloat16 g_xl[(size_t)B_ROWS * K_IN];          // x lo
__device__ __nv_bfloat16 g_wh[(size_t)M_EXP * H1_DIM * K_IN];  // eW1^T hi [m][n][k]
__device__ __nv_bfloat16 g_wl[(size_t)M_EXP * H1_DIM * K_IN];  // eW1^T lo

// bf16 split transposed+padded weights for E2/T2 HMMA path: [batch][96][128]
__device__ __nv_bfloat16 g_w2h[(size_t)M_EXP * 96 * 128];
__device__ __nv_bfloat16 g_w2l[(size_t)M_EXP * 96 * 128];
__device__ __nv_bfloat16 g_tw2h[(size_t)N_TASK * 96 * 128];
__device__ __nv_bfloat16 g_tw2l[(size_t)N_TASK * 96 * 128];

// ---------------------------------------------------------------------------
// Packed f32x2 helpers (Blackwell FFMA2)
// ---------------------------------------------------------------------------
__device__ __forceinline__ void fma2(unsigned long long& d,
                                     unsigned long long a,
                                     unsigned long long b) {
    asm("fma.rn.f32x2 %0, %1, %2, %0;" : "+l"(d) : "l"(a), "l"(b));
}
__device__ __forceinline__ unsigned long long dup2(float x) {
    unsigned long long r;
    unsigned int xi = __float_as_uint(x);
    asm("mov.b64 %0, {%1, %1};" : "=l"(r) : "r"(xi));
    return r;
}
__device__ __forceinline__ unsigned long long pack2(float lo, float hi) {
    unsigned long long r;
    asm("mov.b64 %0, {%1, %2};" : "=l"(r)
        : "r"(__float_as_uint(lo)), "r"(__float_as_uint(hi)));
    return r;
}
__device__ __forceinline__ void unpack2(unsigned long long v, float& lo, float& hi) {
    unsigned int a, b;
    asm("mov.b64 {%0, %1}, %2;" : "=r"(a), "=r"(b) : "l"(v));
    lo = __uint_as_float(a);
    hi = __uint_as_float(b);
}

// ---------------------------------------------------------------------------
// PTX helpers (sm_80-era features only: legal at virtual arch compute_103)
// ---------------------------------------------------------------------------
__device__ __forceinline__ uint32_t smem_u32(const void* p) {
    uint32_t a;
    asm("{ .reg .u64 t; cvta.to.shared.u64 t, %1; cvt.u32.u64 %0, t; }"
        : "=r"(a) : "l"(p));
    return a;
}
__device__ __forceinline__ void cp16(uint32_t s, const void* g) {
    asm volatile("cp.async.cg.shared.global [%0], [%1], 16;" :: "r"(s), "l"(g));
}
__device__ __forceinline__ void cp_commit() {
    asm volatile("cp.async.commit_group;" ::: "memory");
}
template<int N> __device__ __forceinline__ void cp_wait() {
    asm volatile("cp.async.wait_group %0;" :: "n"(N) : "memory");
}
__device__ __forceinline__ void ldsm_x4(uint32_t& r0, uint32_t& r1,
                                        uint32_t& r2, uint32_t& r3, uint32_t a) {
    asm volatile("ldmatrix.sync.aligned.m8n8.x4.shared.b16 {%0,%1,%2,%3}, [%4];"
                 : "=r"(r0), "=r"(r1), "=r"(r2), "=r"(r3) : "r"(a));
}
__device__ __forceinline__ void mma_bf16(float& c0, float& c1, float& c2, float& c3,
                                         uint32_t a0, uint32_t a1, uint32_t a2, uint32_t a3,
                                         uint32_t b0, uint32_t b1) {
    asm volatile("mma.sync.aligned.m16n8k16.row.col.f32.bf16.bf16.f32 "
                 "{%0,%1,%2,%3},{%4,%5,%6,%7},{%8,%9},{%0,%1,%2,%3};"
                 : "+f"(c0), "+f"(c1), "+f"(c2), "+f"(c3)
                 : "r"(a0), "r"(a1), "r"(a2), "r"(a3), "r"(b0), "r"(b1));
}

// ---------------------------------------------------------------------------
// Conversion kernels: fp32 -> (bf16 hi, bf16 lo)
// ---------------------------------------------------------------------------
__global__ void convert_x_kernel(const float* __restrict__ x,
                                 __nv_bfloat16* __restrict__ xh,
                                 __nv_bfloat16* __restrict__ xl)
{
    size_t i = (size_t)blockIdx.x * blockDim.x + threadIdx.x;
    const size_t total = (size_t)B_ROWS * K_IN;
    if (i >= total) return;
    float v = x[i];
    __nv_bfloat16 h = __float2bfloat16(v);
    float rem = v - __bfloat162float(h);
    xh[i] = h;
    xl[i] = __float2bfloat16(rem);
}

// eW1 [m][k][n] -> transposed hi/lo [m][n][k]
__global__ void convert_w_kernel(const float* __restrict__ w,
                                 __nv_bfloat16* __restrict__ wh,
                                 __nv_bfloat16* __restrict__ wl)
{
    size_t i = (size_t)blockIdx.x * blockDim.x + threadIdx.x;
    const size_t total = (size_t)M_EXP * K_IN * H1_DIM;
    if (i >= total) return;
    size_t m = i / ((size_t)K_IN * H1_DIM);
    size_t rem = i % ((size_t)K_IN * H1_DIM);
    size_t k = rem / H1_DIM;
    size_t n = rem % H1_DIM;
    float v = w[i];
    __nv_bfloat16 h = __float2bfloat16(v);
    float r2 = v - __bfloat162float(h);
    size_t o = (m * H1_DIM + n) * K_IN + k;
    wh[o] = h;
    wl[o] = __float2bfloat16(r2);
}

// w [b][Kreal][Nreal] -> wh/wl [b][96][128] transposed + zero padded
__global__ void convert_w2_kernel(const float* __restrict__ w, int batchN,
                                  int Kreal, int Nreal,
                                  __nv_bfloat16* __restrict__ wh,
                                  __nv_bfloat16* __restrict__ wl)
{
    size_t i = (size_t)blockIdx.x * blockDim.x + threadIdx.x;
    size_t total = (size_t)batchN * 96 * 128;
    if (i >= total) return;
    int k = (int)(i % 128);
    int n = (int)((i / 128) % 96);
    int b = (int)(i / (128 * 96));
    float v = (k < Kreal && n < Nreal) ? w[((size_t)b * Kreal + k) * Nreal + n] : 0.f;
    __nv_bfloat16 h = __float2bfloat16(v);
    wh[i] = h;
    wl[i] = __float2bfloat16(v - __bfloat162float(h));
}

// ---------------------------------------------------------------------------
// E1 HMMA kernel: H1[m][r][120] = relu(x[r,:] @ eW1[m] + eb1[m])
// bf16-split 3-pass mma.sync.m16n8k16, BM=128, BN=128(pad of 120), BK=32.
// Single __syncthreads per k-chunk:
//   cp_wait<0> -> sync -> issue load(c+1) -> compute(c)
// grid = (M_EXP, B_ROWS/128)
// ---------------------------------------------------------------------------
#define E1_BK        32
#define E1_NC        (K_IN / E1_BK)     // 128 iters
#define E1_RSTRIDE   80                 // bytes per smem row (40 bf16)
#define E1_AH        0
#define E1_AL        10240
#define E1_BH        20480
#define E1_BL        30720
#define E1_STAGE     40960
#define E1_SMEM      (2 * E1_STAGE)     // 81920 bytes

static __device__ __forceinline__ void e1_load_stage(
    uint32_t sbase, int k0,
    const __nv_bfloat16* __restrict__ xh_t, const __nv_bfloat16* __restrict__ xl_t,
    const __nv_bfloat16* __restrict__ wh_m, const __nv_bfloat16* __restrict__ wl_m,
    int t)
{
    #pragma unroll
    for (int i = 0; i < 2; i++) {
        int u = t + i * 256;          // 0..511
        int r = u >> 2, c4 = u & 3;
        uint32_t dst = sbase + r * E1_RSTRIDE + c4 * 16;
        cp16(dst + E1_AH, xh_t + (size_t)r * K_IN + k0 + c4 * 8);
        cp16(dst + E1_AL, xl_t + (size_t)r * K_IN + k0 + c4 * 8);
    }
    #pragma unroll
    for (int i = 0; i < 2; i++) {
        int u = t + i * 256;
        if (u < 480) {
            int r = u >> 2, c4 = u & 3;
            uint32_t dst = sbase + r * E1_RSTRIDE + c4 * 16;
            cp16(dst + E1_BH, wh_m + (size_t)r * K_IN + k0 + c4 * 8);
            cp16(dst + E1_BL, wl_m + (size_t)r * K_IN + k0 + c4 * 8);
        }
    }
}

__global__ __launch_bounds__(256)
void e1_mma_kernel(const __nv_bfloat16* __restrict__ xh,
                   const __nv_bfloat16* __restrict__ xl,
                   const __nv_bfloat16* __restrict__ wh,
                   const __nv_bfloat16* __restrict__ wl,
                   const float* __restrict__ eb1,
                   float* __restrict__ H1)
{
    extern __shared__ char smem[];
    const uint32_t sb = smem_u32(smem);
    const int t    = threadIdx.x;
    const int lane = t & 31;
    const int wid  = t >> 5;
    const int wm   = wid >> 1;   // 0..3 (m-dim)
    const int wn   = wid & 1;    // 0..1 (n-dim)

    const int m  = blockIdx.x;
    const int r0 = blockIdx.y * 128;

    const __nv_bfloat16* xh_t = xh + (size_t)r0 * K_IN;
    const __nv_bfloat16* xl_t = xl + (size_t)r0 * K_IN;
    const __nv_bfloat16* wh_m = wh + (size_t)m * H1_DIM * K_IN;
    const __nv_bfloat16* wl_m = wl + (size_t)m * H1_DIM * K_IN;

    // zero the B pad rows (120..127) in both stages, both matrices
    for (int u = t; u < 8 * 20 * 2 * 2; u += 256) {
        int w32  = u % 160;
        int mat  = (u / 160) & 1;
        int stg  = (u / 320);
        int r    = 120 + (w32 / 20);
        int c    = w32 % 20;
        *reinterpret_cast<uint32_t*>(smem + stg * E1_STAGE +
            (mat ? E1_BL : E1_BH) + r * E1_RSTRIDE + c * 4) = 0u;
    }

    float acc[2][8][4];
    #pragma unroll
    for (int i = 0; i < 2; i++)
        #pragma unroll
        for (int j = 0; j < 8; j++)
            #pragma unroll
            for (int q = 0; q < 4; q++)
                acc[i][j][q] = 0.f;

    const uint32_t a_base = (uint32_t)((wm * 32 + (lane & 15)) * E1_RSTRIDE +
                                       (lane >> 4) * 16);
    const uint32_t b_base = (uint32_t)((wn * 64 + (lane & 15)) * E1_RSTRIDE +
                                       (lane >> 4) * 16);

    // prologue: chunk 0 -> stage 0
    e1_load_stage(sb, 0, xh_t, xl_t, wh_m, wl_m, t);
    cp_commit();

    for (int c = 0; c < E1_NC; c++) {
        const int s = c & 1;
        cp_wait<0>();            // my copies of chunk c done
        __syncthreads();         // everyone's done + stage s^1 compute finished
        if (c + 1 < E1_NC) {     // prefetch next chunk into the other stage
            e1_load_stage(sb + (s ^ 1) * E1_STAGE, (c + 1) * E1_BK,
                          xh_t, xl_t, wh_m, wl_m, t);
            cp_commit();
        }

        const uint32_t stg = sb + s * E1_STAGE;
        #pragma unroll
        for (int ks = 0; ks < 2; ks++) {
            const uint32_t ko = ks * 32;
            uint32_t ah[2][4], al[2][4];
            #pragma unroll
            for (int mt = 0; mt < 2; mt++) {
                uint32_t ad = stg + a_base + mt * (16 * E1_RSTRIDE) + ko;
                ldsm_x4(ah[mt][0], ah[mt][1], ah[mt][2], ah[mt][3], ad + E1_AH);
                ldsm_x4(al[mt][0], al[mt][1], al[mt][2], al[mt][3], ad + E1_AL);
            }
            uint32_t bh[4][4], bl[4][4];
            #pragma unroll
            for (int g = 0; g < 4; g++) {
                uint32_t bd = stg + b_base + g * (16 * E1_RSTRIDE) + ko;
                ldsm_x4(bh[g][0], bh[g][1], bh[g][2], bh[g][3], bd + E1_BH);
                ldsm_x4(bl[g][0], bl[g][1], bl[g][2], bl[g][3], bd + E1_BL);
            }
            #pragma unroll
            for (int mt = 0; mt < 2; mt++) {
                #pragma unroll
                for (int nt = 0; nt < 8; nt++) {
                    const int g = nt >> 1, p = (nt & 1);
                    float* cc = acc[mt][nt];
                    mma_bf16(cc[0], cc[1], cc[2], cc[3],
                             ah[mt][0], ah[mt][1], ah[mt][2], ah[mt][3],
                             bh[g][p], bh[g][p + 2]);
                    mma_bf16(cc[0], cc[1], cc[2], cc[3],
                             ah[mt][0], ah[mt][1], ah[mt][2], ah[mt][3],
                             bl[g][p], bl[g][p + 2]);
                    mma_bf16(cc[0], cc[1], cc[2], cc[3],
                             al[mt][0], al[mt][1], al[mt][2], al[mt][3],
                             bh[g][p], bh[g][p + 2]);
                }
            }
        }
    }

    // epilogue: bias + relu, direct fp32 stores
    const float* bias = eb1 + (size_t)m * H1_DIM;
    const int row_base = r0 + wm * 32 + (lane >> 2);
    const int col_base = wn * 64 + (lane & 3) * 2;
    #pragma unroll
    for (int mt = 0; mt < 2; mt++) {
        #pragma unroll
        for (int half = 0; half < 2; half++) {
            const int r = row_base + mt * 16 + half * 8;
            float* dst = H1 + ((size_t)m * B_ROWS + r) * H1_DIM;
            #pragma unroll
            for (int nt = 0; nt < 8; nt++) {
                const int ccol = col_base + nt * 8;
                if (ccol < H1_DIM) {
                    float2 v;
                    v.x = fmaxf(acc[mt][nt][half * 2 + 0] + bias[ccol], 0.f);
                    v.y = fmaxf(acc[mt][nt][half * 2 + 1] + bias[ccol + 1], 0.f);
                    *reinterpret_cast<float2*>(dst + ccol) = v;
                }
            }
        }
    }
}

// ---------------------------------------------------------------------------
// Fused two-layer HMMA kernel (used for E2+E3 and T2+T3):
//   Mid = relu(A[b][r][0:120] @ W2[b] + b2[b])      (HMMA, bf16-split)
//   Out[b][r][0:10] = Mid @ W3[b] + b3[b]           (SIMT epilogue from smem)
// A fp32 (lda=120) converted to bf16 hi/lo in-kernel. W2 pre-converted
// transposed padded [b][96][128] hi/lo.  K padded to 128 (4 iters of 32).
// grid = (batch, 64), 256 threads.
// ---------------------------------------------------------------------------
#define G2_KP      128
#define G2_KR      120
#define G2_NP      96
#define G2_NR      84
#define G2_RS      80                   // smem row stride bytes (bf16 tiles)
#define G2_RAW     0                    // 128 rows * 128B fp32 = 16384
#define G2_AH      16384
#define G2_AL      26624
#define G2_BH      36864
#define G2_BL      44544
#define G2_SMEM    52224
// epilogue regions (reuse of dead tile memory after the MMA loop):
#define G2_MIDS    0                    // 128 rows * 90 floats * 4B = 46080
#define G2_MSTR    90                   // mid smem row stride (floats)
#define G2_W3S     46080                // 84*10*4 = 3360  (46080+3360 <= 52224)

__global__ __launch_bounds__(256)
void mma_gemm_fused2_kernel(const float* __restrict__ A, long long aBatch,
                            const __nv_bfloat16* __restrict__ Wh,
                            const __nv_bfloat16* __restrict__ Wl,
                            const float* __restrict__ bias2,
                            const float* __restrict__ W3,
                            const float* __restrict__ bias3,
                            float* __restrict__ Out, long long outBatch)
{
    extern __shared__ char smem[];
    const uint32_t sb = smem_u32(smem);
    const int t    = threadIdx.x;
    const int lane = t & 31;
    const int wid  = t >> 5;
    const int wm   = wid >> 1;
    const int wn   = wid & 1;

    const int batch = blockIdx.x;
    const int r0    = blockIdx.y * 128;

    const float* Ab = A + (long long)batch * aBatch + (size_t)r0 * G2_KR;
    const __nv_bfloat16* WhB = Wh + (size_t)batch * G2_NP * G2_KP;
    const __nv_bfloat16* WlB = Wl + (size_t)batch * G2_NP * G2_KP;

    float acc[2][6][4];
    #pragma unroll
    for (int i = 0; i < 2; i++)
        #pragma unroll
        for (int j = 0; j < 6; j++)
            #pragma unroll
            for (int q = 0; q < 4; q++)
                acc[i][j][q] = 0.f;

    const uint32_t a_base = (uint32_t)((wm * 32 + (lane & 15)) * G2_RS +
                                       (lane >> 4) * 16);
    const uint32_t b_base = (uint32_t)((wn * 48 + (lane & 15)) * G2_RS +
                                       (lane >> 4) * 16);

    for (int it = 0; it < 4; it++) {
        const int k0 = it * 32;
        // ---- load raw A fp32 ----
        #pragma unroll
        for (int i = 0; i < 4; i++) {
            int u = t + i * 256;
            int r = u >> 3, c4 = u & 7;
            int k = k0 + c4 * 4;
            if (k < G2_KR) {
                cp16(sb + G2_RAW + r * 128 + c4 * 16, Ab + (size_t)r * G2_KR + k);
            } else {
                *reinterpret_cast<uint4*>(smem + G2_RAW + r * 128 + c4 * 16) =
                    make_uint4(0u, 0u, 0u, 0u);
            }
        }
        // ---- load B hi/lo ----
        #pragma unroll
        for (int i = 0; i < 3; i++) {
            int u = t + i * 256;
            int mat = u / 384;
            int v = u % 384;
            int rr = v >> 2, c4 = v & 3;
            uint32_t dst = sb + (mat ? G2_BL : G2_BH) + rr * G2_RS + c4 * 16;
            const __nv_bfloat16* src =
                (mat ? WlB : WhB) + (size_t)rr * G2_KP + k0 + c4 * 8;
            cp16(dst, src);
        }
        cp_commit();
        cp_wait<0>();
        __syncthreads();

        // ---- convert raw fp32 -> Ah/Al ----
        #pragma unroll
        for (int j = 0; j < 8; j++) {
            int e = t + j * 256;
            int r = e >> 4, cp2 = e & 15;
            float2 v = *reinterpret_cast<const float2*>(
                smem + G2_RAW + r * 128 + cp2 * 8);
            __nv_bfloat16 h0 = __float2bfloat16(v.x);
            __nv_bfloat16 h1 = __float2bfloat16(v.y);
            float l0 = v.x - __bfloat162float(h0);
            float l1 = v.y - __bfloat162float(h1);
            __nv_bfloat162 hh; hh.x = h0; hh.y = h1;
            __nv_bfloat162 ll; ll.x = __float2bfloat16(l0); ll.y = __float2bfloat16(l1);
            *reinterpret_cast<__nv_bfloat162*>(smem + G2_AH + r * G2_RS + cp2 * 4) = hh;
            *reinterpret_cast<__nv_bfloat162*>(smem + G2_AL + r * G2_RS + cp2 * 4) = ll;
        }
        __syncthreads();

        // ---- MMA ----
        #pragma unroll
        for (int ks = 0; ks < 2; ks++) {
            const uint32_t ko = ks * 32;
            uint32_t ah[2][4], al[2][4];
            #pragma unroll
            for (int mt = 0; mt < 2; mt++) {
                uint32_t ad = sb + a_base + mt * (16 * G2_RS) + ko;
                ldsm_x4(ah[mt][0], ah[mt][1], ah[mt][2], ah[mt][3], ad + G2_AH);
                ldsm_x4(al[mt][0], al[mt][1], al[mt][2], al[mt][3], ad + G2_AL);
            }
            uint32_t bh[3][4], bl[3][4];
            #pragma unroll
            for (int g = 0; g < 3; g++) {
                uint32_t bd = sb + b_base + g * (16 * G2_RS) + ko;
                ldsm_x4(bh[g][0], bh[g][1], bh[g][2], bh[g][3], bd + G2_BH);
                ldsm_x4(bl[g][0], bl[g][1], bl[g][2], bl[g][3], bd + G2_BL);
            }
            #pragma unroll
            for (int mt = 0; mt < 2; mt++) {
                #pragma unroll
                for (int nt = 0; nt < 6; nt++) {
                    const int g = nt >> 1, p = (nt & 1);
                    float* cc = acc[mt][nt];
                    mma_bf16(cc[0], cc[1], cc[2], cc[3],
                             ah[mt][0], ah[mt][1], ah[mt][2], ah[mt][3],
                             bh[g][p], bh[g][p + 2]);
                    mma_bf16(cc[0], cc[1], cc[2], cc[3],
                             ah[mt][0], ah[mt][1], ah[mt][2], ah[mt][3],
                             bl[g][p], bl[g][p + 2]);
                    mma_bf16(cc[0], cc[1], cc[2], cc[3],
                             al[mt][0], al[mt][1], al[mt][2], al[mt][3],
                             bh[g][p], bh[g][p + 2]);
                }
            }
        }
        __syncthreads();
    }

    // ---- fused epilogue 1: relu(acc + bias2) -> smem Mid tile ----
    float* mids = reinterpret_cast<float*>(smem) + G2_MIDS / 4;
    float* w3s  = reinterpret_cast<float*>(smem) + G2_W3S / 4;
    const float* b2 = bias2 + (size_t)batch * G2_NR;
    {
        // W3 -> smem (840 floats), concurrent with Mid writes
        const float* w3g = W3 + (size_t)batch * (G2_NR * T_OUT);
        for (int i = t; i < G2_NR * T_OUT; i += 256) w3s[i] = w3g[i];

        const int rl = wm * 32 + (lane >> 2);
        const int cb = wn * 48 + (lane & 3) * 2;
        #pragma unroll
        for (int mt = 0; mt < 2; mt++) {
            #pragma unroll
            for (int half = 0; half < 2; half++) {
                const int r = rl + mt * 16 + half * 8;
                float* row = mids + r * G2_MSTR;
                #pragma unroll
                for (int nt = 0; nt < 6; nt++) {
                    const int ccol = cb + nt * 8;
                    if (ccol < G2_NR) {
                        float2 v;
                        v.x = fmaxf(acc[mt][nt][half * 2 + 0] + b2[ccol], 0.f);
                        v.y = fmaxf(acc[mt][nt][half * 2 + 1] + b2[ccol + 1], 0.f);
                        *reinterpret_cast<float2*>(row + ccol) = v;
                    }
                }
            }
        }
    }
    __syncthreads();

    // ---- fused epilogue 2: Out = Mid @ W3 + bias3 ----
    {
        const int r  = t >> 1;
        const int c0 = (t & 1) * 5;
        const float* b3 = bias3 + (size_t)batch * T_OUT;
        float a[5];
        #pragma unroll
        for (int j = 0; j < 5; j++) a[j] = b3[c0 + j];
        const float* row = mids + r * G2_MSTR;
        for (int k = 0; k < G2_NR; k++) {
            float tv = row[k];
            #pragma unroll
            for (int j = 0; j < 5; j++)
                a[j] = fmaf(tv, w3s[k * T_OUT + c0 + j], a[j]);
        }
        float* dst = Out + (long long)batch * outBatch +
                     (size_t)(r0 + r) * T_OUT + c0;
        #pragma unroll
        for (int j = 0; j < 5; j++) dst[j] = a[j];
    }
}

// ---------------------------------------------------------------------------
// Fused gate + T1 kernel:
//   G[r][f]  = sum_m (gate_w[m][n]*mask[m][n]) * EO[m][r0+r][f]
//   T1[n][r][h] = relu(sum_f G[r][f]*tW1[n][f][h] + tb1[n][h])
// grid = (N_TASK, 64), 256 threads.
// ---------------------------------------------------------------------------
__global__ __launch_bounds__(256)
void gate_t1_kernel(const float* __restrict__ EO,
                    const float* __restrict__ gw,
                    const int*   __restrict__ gm,
                    const float* __restrict__ tW1,
                    const float* __restrict__ tb1,
                    float* __restrict__ T1out)
{
    __shared__ float Gs[128 * F_CONN];      // 5120B
    __shared__ float W1s[F_CONN * 120];     // 4800B

    const int t  = threadIdx.x;
    const int n  = blockIdx.x;
    const int r0 = blockIdx.y * 128;

    // per-thread effective gate weights
    float w[M_EXP];
    #pragma unroll
    for (int m = 0; m < M_EXP; m++)
        w[m] = gw[m * N_TASK + n] * (float)gm[m * N_TASK + n];

    // gate combine (coalesced EO reads, L2-resident)
    for (int i = t; i < 128 * F_CONN; i += 256) {
        float acc = 0.f;
        #pragma unroll
        for (int m = 0; m < M_EXP; m++)
            acc = fmaf(w[m], EO[((size_t)m * B_ROWS + r0) * F_CONN + i], acc);
        Gs[i] = acc;
    }
    for (int i = t; i < F_CONN * 120; i += 256)
        W1s[i] = tW1[(size_t)n * F_CONN * 120 + i];
    __syncthreads();

    // T1: each thread = (row, 60-col half); FFMA2 over packed col pairs
    const int r  = t >> 1;
    const int h0 = (t & 1) * 60;
    float g[F_CONN];
    #pragma unroll
    for (int f = 0; f < F_CONN; f++) g[f] = Gs[r * F_CONN + f];

    unsigned long long a2[30];
    const float* b1 = tb1 + (size_t)n * 120 + h0;
    #pragma unroll
    for (int j = 0; j < 30; j++) a2[j] = pack2(b1[2 * j], b1[2 * j + 1]);
    #pragma unroll
    for (int f = 0; f < F_CONN; f++) {
        unsigned long long gv = dup2(g[f]);
        const unsigned long long* wrow =
            reinterpret_cast<const unsigned long long*>(W1s + f * 120 + h0);
        #pragma unroll
        for (int j = 0; j < 30; j++) fma2(a2[j], gv, wrow[j]);
    }
    float* dst = T1out + ((size_t)n * B_ROWS + r0 + r) * 120 + h0;
    #pragma unroll
    for (int j = 0; j < 30; j += 2) {
        float x0, x1, x2, x3;
        unpack2(a2[j], x0, x1);
        unpack2(a2[j + 1], x2, x3);
        float4 v;
        v.x = fmaxf(x0, 0.f); v.y = fmaxf(x1, 0.f);
        v.z = fmaxf(x2, 0.f); v.w = fmaxf(x3, 0.f);
        *reinterpret_cast<float4*>(dst + 2 * j) = v;
    }
}

// ---------------------------------------------------------------------------
// logits_loss[n] = sum_m log_sigmoid(gate_logits[m][n])
// ---------------------------------------------------------------------------
__global__ void logits_kernel(const float* __restrict__ gl, float* __restrict__ out)
{
    int n = blockIdx.x * blockDim.x + threadIdx.x;
    if (n >= N_TASK) return;
    float acc = 0.f;
    #pragma unroll
    for (int m = 0; m < M_EXP; m++) {
        float v = gl[m * N_TASK + n];
        float ls = (v > 0.f) ? (-log1pf(expf(-v))) : (v - log1pf(expf(v)));
        acc += ls;
    }
    out[n] = acc;
}

// ---------------------------------------------------------------------------
// kernel_launch
// ---------------------------------------------------------------------------
extern "C" void kernel_launch(void* const* d_in, const int* in_sizes, int n_in,
                              void* d_out, int out_size)
{
    const float* x   = (const float*)d_in[0];
    const float* eW1 = (const float*)d_in[2];
    const float* eb1 = (const float*)d_in[3];
    const float* eW2 = (const float*)d_in[4];
    const float* eb2 = (const float*)d_in[5];
    const float* eW3 = (const float*)d_in[6];
    const float* eb3 = (const float*)d_in[7];
    const float* gw  = (const float*)d_in[8];
    const float* gl  = (const float*)d_in[9];
    const int*   gm  = (const int*)  d_in[10];
    const float* tW1 = (const float*)d_in[11];
    const float* tb1 = (const float*)d_in[12];
    const float* tW2 = (const float*)d_in[13];
    const float* tb2 = (const float*)d_in[14];
    const float* tW3 = (const float*)d_in[15];
    const float* tb3 = (const float*)d_in[16];
    float* out = (float*)d_out;

    float *H1, *EO, *T1b;
    __nv_bfloat16 *xh, *xl, *wh, *wl, *w2h, *w2l, *tw2h, *tw2l;
    cudaGetSymbolAddress((void**)&H1,  g_H1);
    cudaGetSymbolAddress((void**)&EO,  g_EO);
    cudaGetSymbolAddress((void**)&T1b, g_T1);
    cudaGetSymbolAddress((void**)&xh,  g_xh);
    cudaGetSymbolAddress((void**)&xl,  g_xl);
    cudaGetSymbolAddress((void**)&wh,  g_wh);
    cudaGetSymbolAddress((void**)&wl,  g_wl);
    cudaGetSymbolAddress((void**)&w2h, g_w2h);
    cudaGetSymbolAddress((void**)&w2l, g_w2l);
    cudaGetSymbolAddress((void**)&tw2h, g_tw2h);
    cudaGetSymbolAddress((void**)&tw2l, g_tw2l);

    cudaFuncSetAttribute(e1_mma_kernel,
                         cudaFuncAttributeMaxDynamicSharedMemorySize, E1_SMEM);
    cudaFuncSetAttribute(mma_gemm_fused2_kernel,
                         cudaFuncAttributeMaxDynamicSharedMemorySize, G2_SMEM);

    const dim3 blk(256);
    const int rowTiles = B_ROWS / 128;   // 64

    // ---- conversions ----
    {
        size_t nx = (size_t)B_ROWS * K_IN;
        convert_x_kernel<<<(unsigned)((nx + 255) / 256), 256>>>(x, xh, xl);
        size_t nw = (size_t)M_EXP * K_IN * H1_DIM;
        convert_w_kernel<<<(unsigned)((nw + 255) / 256), 256>>>(eW1, wh, wl);
        size_t n2 = (size_t)M_EXP * 96 * 128;
        convert_w2_kernel<<<(unsigned)((n2 + 255) / 256), 256>>>(
            eW2, M_EXP, 120, 84, w2h, w2l);
        size_t n3 = (size_t)N_TASK * 96 * 128;
        convert_w2_kernel<<<(unsigned)((n3 + 255) / 256), 256>>>(
            tW2, N_TASK, 120, 84, tw2h, tw2l);
    }

    // ---- E1 (HMMA, bf16-split 3-pass) -> H1 ----
    e1_mma_kernel<<<dim3(M_EXP, rowTiles), blk, E1_SMEM>>>(
        xh, xl, wh, wl, eb1, H1);

    // ---- E2+E3 fused (HMMA + SIMT tail): H1 -> EO ----
    mma_gemm_fused2_kernel<<<dim3(M_EXP, rowTiles), blk, G2_SMEM>>>(
        H1, (long long)B_ROWS * 120, w2h, w2l, eb2,
        eW3, eb3, EO, (long long)B_ROWS * T_OUT);

    // ---- gate + T1 fused: EO -> T1b ----
    gate_t1_kernel<<<dim3(N_TASK, rowTiles), blk>>>(
        EO, gw, gm, tW1, tb1, T1b);

    // ---- T2+T3 fused (HMMA + SIMT tail): T1b -> out ----
    mma_gemm_fused2_kernel<<<dim3(N_TASK, rowTiles), blk, G2_SMEM>>>(
        T1b, (long long)B_ROWS * 120, tw2h, tw2l, tb2,
        tW3, tb3, out, (long long)B_ROWS * T_OUT);

    // logits_loss -> out tail
    logits_kernel<<<1, 128>>>(gl, out + (long long)N_TASK * B_ROWS * T_OUT);
}

// round 7
// speedup vs baseline: 2.7708x; 1.1565x over previous
#include <cuda_runtime.h>
#include <cuda_bf16.h>
#include <cstdint>
#include <math.h>

// ---------------------------------------------------------------------------
// Problem constants
// ---------------------------------------------------------------------------
#define B_ROWS   8192
#define M_EXP    10
#define N_TASK   100
#define F_CONN   10
#define T_OUT    10
#define K_IN     4096
#define H1_DIM   120

// E1 packing geometry
#define E1_BK        32
#define E1_NC        (K_IN / E1_BK)     // 128 chunks
#define NTILES       (B_ROWS / 128)     // 64 row tiles
#define PK_COLS      40                 // 32 data bf16 + 8 pad -> 80B rows

// ---------------------------------------------------------------------------
// Scratch (device globals: allocation-free rule workaround)
// ---------------------------------------------------------------------------
__device__ float g_H1[(size_t)M_EXP * B_ROWS * 120];   // expert layer-1 out
__device__ float g_EO[(size_t)M_EXP * B_ROWS * 10];    // expert out [M,B,F]
__device__ float g_T1[(size_t)N_TASK * B_ROWS * 120];  // task layer-1 out

// chunk-major packed hi/lo for E1 bulk loads:
// x:  [chunk 128][tile 64][row 128][40 bf16]   (80B row stride, pad garbage->0)
// w:  [m 10][chunk 128][n 128 (120 real, pad 0)][40 bf16]
__device__ __nv_bfloat16 g_xph[(size_t)E1_NC * B_ROWS * PK_COLS];
__device__ __nv_bfloat16 g_xpl[(size_t)E1_NC * B_ROWS * PK_COLS];
__device__ __nv_bfloat16 g_wph[(size_t)M_EXP * E1_NC * 128 * PK_COLS];
__device__ __nv_bfloat16 g_wpl[(size_t)M_EXP * E1_NC * 128 * PK_COLS];

// bf16 split transposed+padded weights for E2/T2 HMMA path: [batch][96][128]
__device__ __nv_bfloat16 g_w2h[(size_t)M_EXP * 96 * 128];
__device__ __nv_bfloat16 g_w2l[(size_t)M_EXP * 96 * 128];
__device__ __nv_bfloat16 g_tw2h[(size_t)N_TASK * 96 * 128];
__device__ __nv_bfloat16 g_tw2l[(size_t)N_TASK * 96 * 128];

// ---------------------------------------------------------------------------
// Packed f32x2 helpers (Blackwell FFMA2)
// ---------------------------------------------------------------------------
__device__ __forceinline__ void fma2(unsigned long long& d,
                                     unsigned long long a,
                                     unsigned long long b) {
    asm("fma.rn.f32x2 %0, %1, %2, %0;" : "+l"(d) : "l"(a), "l"(b));
}
__device__ __forceinline__ unsigned long long dup2(float x) {
    unsigned long long r;
    unsigned int xi = __float_as_uint(x);
    asm("mov.b64 %0, {%1, %1};" : "=l"(r) : "r"(xi));
    return r;
}
__device__ __forceinline__ unsigned long long pack2(float lo, float hi) {
    unsigned long long r;
    asm("mov.b64 %0, {%1, %2};" : "=l"(r)
        : "r"(__float_as_uint(lo)), "r"(__float_as_uint(hi)));
    return r;
}
__device__ __forceinline__ void unpack2(unsigned long long v, float& lo, float& hi) {
    unsigned int a, b;
    asm("mov.b64 {%0, %1}, %2;" : "=r"(a), "=r"(b) : "l"(v));
    lo = __uint_as_float(a);
    hi = __uint_as_float(b);
}

// ---------------------------------------------------------------------------
// PTX helpers (<= sm_90 baseline features: legal at virtual arch compute_103)
// ---------------------------------------------------------------------------
__device__ __forceinline__ uint32_t smem_u32(const void* p) {
    uint32_t a;
    asm("{ .reg .u64 t; cvta.to.shared.u64 t, %1; cvt.u32.u64 %0, t; }"
        : "=r"(a) : "l"(p));
    return a;
}
__device__ __forceinline__ void cp16(uint32_t s, const void* g) {
    asm volatile("cp.async.cg.shared.global [%0], [%1], 16;" :: "r"(s), "l"(g));
}
__device__ __forceinline__ void cp_commit() {
    asm volatile("cp.async.commit_group;" ::: "memory");
}
template<int N> __device__ __forceinline__ void cp_wait() {
    asm volatile("cp.async.wait_group %0;" :: "n"(N) : "memory");
}
__device__ __forceinline__ void mbar_init(uint32_t mb, uint32_t cnt) {
    asm volatile("mbarrier.init.shared.b64 [%0], %1;" :: "r"(mb), "r"(cnt) : "memory");
}
__device__ __forceinline__ void mbar_expect_tx(uint32_t mb, uint32_t bytes) {
    asm volatile("mbarrier.arrive.expect_tx.shared.b64 _, [%0], %1;"
                 :: "r"(mb), "r"(bytes) : "memory");
}
__device__ __forceinline__ void mbar_wait(uint32_t mb, uint32_t parity) {
    asm volatile("{\n\t.reg .pred P;\n"
                 "W%=:\n\t"
                 "mbarrier.try_wait.parity.acquire.cta.shared::cta.b64 P, [%0], %1, 0x989680;\n\t"
                 "@P bra D%=;\n\t"
                 "bra W%=;\n"
                 "D%=:\n\t}"
                 :: "r"(mb), "r"(parity) : "memory");
}
__device__ __forceinline__ void bulk_g2s(uint32_t dst, const void* src,
                                         uint32_t bytes, uint32_t mb) {
    asm volatile("cp.async.bulk.shared::cta.global.mbarrier::complete_tx::bytes "
                 "[%0], [%1], %2, [%3];"
                 :: "r"(dst), "l"(src), "r"(bytes), "r"(mb) : "memory");
}
__device__ __forceinline__ void ldsm_x4(uint32_t& r0, uint32_t& r1,
                                        uint32_t& r2, uint32_t& r3, uint32_t a) {
    asm volatile("ldmatrix.sync.aligned.m8n8.x4.shared.b16 {%0,%1,%2,%3}, [%4];"
                 : "=r"(r0), "=r"(r1), "=r"(r2), "=r"(r3) : "r"(a));
}
__device__ __forceinline__ void mma_bf16(float& c0, float& c1, float& c2, float& c3,
                                         uint32_t a0, uint32_t a1, uint32_t a2, uint32_t a3,
                                         uint32_t b0, uint32_t b1) {
    asm volatile("mma.sync.aligned.m16n8k16.row.col.f32.bf16.bf16.f32 "
                 "{%0,%1,%2,%3},{%4,%5,%6,%7},{%8,%9},{%0,%1,%2,%3};"
                 : "+f"(c0), "+f"(c1), "+f"(c2), "+f"(c3)
                 : "r"(a0), "r"(a1), "r"(a2), "r"(a3), "r"(b0), "r"(b1));
}

// ---------------------------------------------------------------------------
// Packing kernels for E1 bulk loads
// ---------------------------------------------------------------------------
// x [8192][4096] fp32 -> xph/xpl [chunk][row-global][40] bf16
__global__ void pack_x_kernel(const float* __restrict__ x,
                              __nv_bfloat16* __restrict__ xph,
                              __nv_bfloat16* __restrict__ xpl)
{
    size_t i = (size_t)blockIdx.x * blockDim.x + threadIdx.x;
    const size_t total = (size_t)E1_NC * B_ROWS * PK_COLS;
    if (i >= total) return;
    int col = (int)(i % PK_COLS);
    int row = (int)((i / PK_COLS) % B_ROWS);
    int c   = (int)(i / ((size_t)PK_COLS * B_ROWS));
    float v = 0.f;
    if (col < E1_BK) v = x[(size_t)row * K_IN + c * E1_BK + col];
    __nv_bfloat16 h = __float2bfloat16(v);
    xph[i] = h;
    xpl[i] = __float2bfloat16(v - __bfloat162float(h));
}

// eW1 [m][4096][120] fp32 -> wph/wpl [m][chunk][128 n][40] bf16 (n>=120 -> 0)
__global__ void pack_w_kernel(const float* __restrict__ w,
                              __nv_bfloat16* __restrict__ wph,
                              __nv_bfloat16* __restrict__ wpl)
{
    size_t i = (size_t)blockIdx.x * blockDim.x + threadIdx.x;
    const size_t total = (size_t)M_EXP * E1_NC * 128 * PK_COLS;
    if (i >= total) return;
    int col = (int)(i % PK_COLS);
    int n   = (int)((i / PK_COLS) % 128);
    int c   = (int)((i / ((size_t)PK_COLS * 128)) % E1_NC);
    int m   = (int)(i / ((size_t)PK_COLS * 128 * E1_NC));
    float v = 0.f;
    if (col < E1_BK && n < H1_DIM)
        v = w[((size_t)m * K_IN + c * E1_BK + col) * H1_DIM + n];
    __nv_bfloat16 h = __float2bfloat16(v);
    wph[i] = h;
    wpl[i] = __float2bfloat16(v - __bfloat162float(h));
}

// w [b][Kreal][Nreal] -> wh/wl [b][96][128] transposed + zero padded
__global__ void convert_w2_kernel(const float* __restrict__ w, int batchN,
                                  int Kreal, int Nreal,
                                  __nv_bfloat16* __restrict__ wh,
                                  __nv_bfloat16* __restrict__ wl)
{
    size_t i = (size_t)blockIdx.x * blockDim.x + threadIdx.x;
    size_t total = (size_t)batchN * 96 * 128;
    if (i >= total) return;
    int k = (int)(i % 128);
    int n = (int)((i / 128) % 96);
    int b = (int)(i / (128 * 96));
    float v = (k < Kreal && n < Nreal) ? w[((size_t)b * Kreal + k) * Nreal + n] : 0.f;
    __nv_bfloat16 h = __float2bfloat16(v);
    wh[i] = h;
    wl[i] = __float2bfloat16(v - __bfloat162float(h));
}

// ---------------------------------------------------------------------------
// E1 HMMA kernel (bulk-load version):
//   H1[m][r][120] = relu(x[r,:] @ eW1[m] + eb1[m])
// Per chunk: 4 cp.async.bulk (Ah, Al, Bh, Bl; 10240B each) + mbarrier,
// 2-stage pipeline, bf16-split 3-pass mma.sync.m16n8k16.
// grid = (M_EXP, 64), 256 threads.
// ---------------------------------------------------------------------------
#define E1_RSTRIDE   80
#define E1_AH        0
#define E1_AL        10240
#define E1_BH        20480
#define E1_BL        30720
#define E1_STAGE     40960
#define E1_MBAR      81920
#define E1_SMEM      (2 * E1_STAGE + 32)

static __device__ __forceinline__ void e1_issue(
    uint32_t stg, uint32_t mb, int c,
    const __nv_bfloat16* __restrict__ xph, const __nv_bfloat16* __restrict__ xpl,
    const __nv_bfloat16* __restrict__ wph, const __nv_bfloat16* __restrict__ wpl,
    int tileY, int m)
{
    mbar_expect_tx(mb, 4 * 10240);
    const size_t aoff = ((size_t)c * B_ROWS + (size_t)tileY * 128) * PK_COLS;
    const size_t boff = ((size_t)m * E1_NC + c) * 128 * PK_COLS;
    bulk_g2s(stg + E1_AH, xph + aoff, 10240, mb);
    bulk_g2s(stg + E1_AL, xpl + aoff, 10240, mb);
    bulk_g2s(stg + E1_BH, wph + boff, 10240, mb);
    bulk_g2s(stg + E1_BL, wpl + boff, 10240, mb);
}

__global__ __launch_bounds__(256)
void e1_mma_kernel(const __nv_bfloat16* __restrict__ xph,
                   const __nv_bfloat16* __restrict__ xpl,
                   const __nv_bfloat16* __restrict__ wph,
                   const __nv_bfloat16* __restrict__ wpl,
                   const float* __restrict__ eb1,
                   float* __restrict__ H1)
{
    extern __shared__ char smem[];
    const uint32_t sb = smem_u32(smem);
    const int t    = threadIdx.x;
    const int lane = t & 31;
    const int wid  = t >> 5;
    const int wm   = wid >> 1;   // 0..3 (m-dim)
    const int wn   = wid & 1;    // 0..1 (n-dim)

    const int m     = blockIdx.x;
    const int tileY = blockIdx.y;
    const int r0    = tileY * 128;

    const uint32_t mb0 = sb + E1_MBAR;
    const uint32_t mb1 = sb + E1_MBAR + 8;

    if (t == 0) {
        mbar_init(mb0, 1);
        mbar_init(mb1, 1);
    }
    __syncthreads();

    float acc[2][8][4];
    #pragma unroll
    for (int i = 0; i < 2; i++)
        #pragma unroll
        for (int j = 0; j < 8; j++)
            #pragma unroll
            for (int q = 0; q < 4; q++)
                acc[i][j][q] = 0.f;

    const uint32_t a_base = (uint32_t)((wm * 32 + (lane & 15)) * E1_RSTRIDE +
                                       (lane >> 4) * 16);
    const uint32_t b_base = (uint32_t)((wn * 64 + (lane & 15)) * E1_RSTRIDE +
                                       (lane >> 4) * 16);

    uint32_t phase[2] = {0u, 0u};

    // prologue: chunk 0 -> stage 0
    if (t == 0) e1_issue(sb, mb0, 0, xph, xpl, wph, wpl, tileY, m);

    for (int c = 0; c < E1_NC; c++) {
        const int s = c & 1;
        // prefetch chunk c+1 into the other stage (its compute finished at c-1)
        if (c + 1 < E1_NC && t == 0)
            e1_issue(sb + (s ^ 1) * E1_STAGE, s ? mb0 : mb1, c + 1,
                     xph, xpl, wph, wpl, tileY, m);
        // wait chunk c's data
        mbar_wait(s ? mb1 : mb0, phase[s]);
        phase[s] ^= 1u;

        const uint32_t stg = sb + s * E1_STAGE;
        #pragma unroll
        for (int ks = 0; ks < 2; ks++) {
            const uint32_t ko = ks * 32;
            uint32_t ah[2][4], al[2][4];
            #pragma unroll
            for (int mt = 0; mt < 2; mt++) {
                uint32_t ad = stg + a_base + mt * (16 * E1_RSTRIDE) + ko;
                ldsm_x4(ah[mt][0], ah[mt][1], ah[mt][2], ah[mt][3], ad + E1_AH);
                ldsm_x4(al[mt][0], al[mt][1], al[mt][2], al[mt][3], ad + E1_AL);
            }
            uint32_t bh[4][4], bl[4][4];
            #pragma unroll
            for (int g = 0; g < 4; g++) {
                uint32_t bd = stg + b_base + g * (16 * E1_RSTRIDE) + ko;
                ldsm_x4(bh[g][0], bh[g][1], bh[g][2], bh[g][3], bd + E1_BH);
                ldsm_x4(bl[g][0], bl[g][1], bl[g][2], bl[g][3], bd + E1_BL);
            }
            #pragma unroll
            for (int mt = 0; mt < 2; mt++) {
                #pragma unroll
                for (int nt = 0; nt < 8; nt++) {
                    const int g = nt >> 1, p = (nt & 1);
                    float* cc = acc[mt][nt];
                    mma_bf16(cc[0], cc[1], cc[2], cc[3],
                             ah[mt][0], ah[mt][1], ah[mt][2], ah[mt][3],
                             bh[g][p], bh[g][p + 2]);
                    mma_bf16(cc[0], cc[1], cc[2], cc[3],
                             ah[mt][0], ah[mt][1], ah[mt][2], ah[mt][3],
                             bl[g][p], bl[g][p + 2]);
                    mma_bf16(cc[0], cc[1], cc[2], cc[3],
                             al[mt][0], al[mt][1], al[mt][2], al[mt][3],
                             bh[g][p], bh[g][p + 2]);
                }
            }
        }
        __syncthreads();   // all warps done with stage s -> safe to refill next iter
    }

    // epilogue: bias + relu, direct fp32 stores
    const float* bias = eb1 + (size_t)m * H1_DIM;
    const int row_base = r0 + wm * 32 + (lane >> 2);
    const int col_base = wn * 64 + (lane & 3) * 2;
    #pragma unroll
    for (int mt = 0; mt < 2; mt++) {
        #pragma unroll
        for (int half = 0; half < 2; half++) {
            const int r = row_base + mt * 16 + half * 8;
            float* dst = H1 + ((size_t)m * B_ROWS + r) * H1_DIM;
            #pragma unroll
            for (int nt = 0; nt < 8; nt++) {
                const int ccol = col_base + nt * 8;
                if (ccol < H1_DIM) {
                    float2 v;
                    v.x = fmaxf(acc[mt][nt][half * 2 + 0] + bias[ccol], 0.f);
                    v.y = fmaxf(acc[mt][nt][half * 2 + 1] + bias[ccol + 1], 0.f);
                    *reinterpret_cast<float2*>(dst + ccol) = v;
                }
            }
        }
    }
}

// ---------------------------------------------------------------------------
// Fused two-layer HMMA kernel (E2+E3 and T2+T3)  -- unchanged from R6
// ---------------------------------------------------------------------------
#define G2_KP      128
#define G2_KR      120
#define G2_NP      96
#define G2_NR      84
#define G2_RS      80
#define G2_RAW     0
#define G2_AH      16384
#define G2_AL      26624
#define G2_BH      36864
#define G2_BL      44544
#define G2_SMEM    52224
#define G2_MIDS    0
#define G2_MSTR    90
#define G2_W3S     46080

__global__ __launch_bounds__(256)
void mma_gemm_fused2_kernel(const float* __restrict__ A, long long aBatch,
                            const __nv_bfloat16* __restrict__ Wh,
                            const __nv_bfloat16* __restrict__ Wl,
                            const float* __restrict__ bias2,
                            const float* __restrict__ W3,
                            const float* __restrict__ bias3,
                            float* __restrict__ Out, long long outBatch)
{
    extern __shared__ char smem[];
    const uint32_t sb = smem_u32(smem);
    const int t    = threadIdx.x;
    const int lane = t & 31;
    const int wid  = t >> 5;
    const int wm   = wid >> 1;
    const int wn   = wid & 1;

    const int batch = blockIdx.x;
    const int r0    = blockIdx.y * 128;

    const float* Ab = A + (long long)batch * aBatch + (size_t)r0 * G2_KR;
    const __nv_bfloat16* WhB = Wh + (size_t)batch * G2_NP * G2_KP;
    const __nv_bfloat16* WlB = Wl + (size_t)batch * G2_NP * G2_KP;

    float acc[2][6][4];
    #pragma unroll
    for (int i = 0; i < 2; i++)
        #pragma unroll
        for (int j = 0; j < 6; j++)
            #pragma unroll
            for (int q = 0; q < 4; q++)
                acc[i][j][q] = 0.f;

    const uint32_t a_base = (uint32_t)((wm * 32 + (lane & 15)) * G2_RS +
                                       (lane >> 4) * 16);
    const uint32_t b_base = (uint32_t)((wn * 48 + (lane & 15)) * G2_RS +
                                       (lane >> 4) * 16);

    for (int it = 0; it < 4; it++) {
        const int k0 = it * 32;
        #pragma unroll
        for (int i = 0; i < 4; i++) {
            int u = t + i * 256;
            int r = u >> 3, c4 = u & 7;
            int k = k0 + c4 * 4;
            if (k < G2_KR) {
                cp16(sb + G2_RAW + r * 128 + c4 * 16, Ab + (size_t)r * G2_KR + k);
            } else {
                *reinterpret_cast<uint4*>(smem + G2_RAW + r * 128 + c4 * 16) =
                    make_uint4(0u, 0u, 0u, 0u);
            }
        }
        #pragma unroll
        for (int i = 0; i < 3; i++) {
            int u = t + i * 256;
            int mat = u / 384;
            int v = u % 384;
            int rr = v >> 2, c4 = v & 3;
            uint32_t dst = sb + (mat ? G2_BL : G2_BH) + rr * G2_RS + c4 * 16;
            const __nv_bfloat16* src =
                (mat ? WlB : WhB) + (size_t)rr * G2_KP + k0 + c4 * 8;
            cp16(dst, src);
        }
        cp_commit();
        cp_wait<0>();
        __syncthreads();

        #pragma unroll
        for (int j = 0; j < 8; j++) {
            int e = t + j * 256;
            int r = e >> 4, cp2 = e & 15;
            float2 v = *reinterpret_cast<const float2*>(
                smem + G2_RAW + r * 128 + cp2 * 8);
            __nv_bfloat16 h0 = __float2bfloat16(v.x);
            __nv_bfloat16 h1 = __float2bfloat16(v.y);
            float l0 = v.x - __bfloat162float(h0);
            float l1 = v.y - __bfloat162float(h1);
            __nv_bfloat162 hh; hh.x = h0; hh.y = h1;
            __nv_bfloat162 ll; ll.x = __float2bfloat16(l0); ll.y = __float2bfloat16(l1);
            *reinterpret_cast<__nv_bfloat162*>(smem + G2_AH + r * G2_RS + cp2 * 4) = hh;
            *reinterpret_cast<__nv_bfloat162*>(smem + G2_AL + r * G2_RS + cp2 * 4) = ll;
        }
        __syncthreads();

        #pragma unroll
        for (int ks = 0; ks < 2; ks++) {
            const uint32_t ko = ks * 32;
            uint32_t ah[2][4], al[2][4];
            #pragma unroll
            for (int mt = 0; mt < 2; mt++) {
                uint32_t ad = sb + a_base + mt * (16 * G2_RS) + ko;
                ldsm_x4(ah[mt][0], ah[mt][1], ah[mt][2], ah[mt][3], ad + G2_AH);
                ldsm_x4(al[mt][0], al[mt][1], al[mt][2], al[mt][3], ad + G2_AL);
            }
            uint32_t bh[3][4], bl[3][4];
            #pragma unroll
            for (int g = 0; g < 3; g++) {
                uint32_t bd = sb + b_base + g * (16 * G2_RS) + ko;
                ldsm_x4(bh[g][0], bh[g][1], bh[g][2], bh[g][3], bd + G2_BH);
                ldsm_x4(bl[g][0], bl[g][1], bl[g][2], bl[g][3], bd + G2_BL);
            }
            #pragma unroll
            for (int mt = 0; mt < 2; mt++) {
                #pragma unroll
                for (int nt = 0; nt < 6; nt++) {
                    const int g = nt >> 1, p = (nt & 1);
                    float* cc = acc[mt][nt];
                    mma_bf16(cc[0], cc[1], cc[2], cc[3],
                             ah[mt][0], ah[mt][1], ah[mt][2], ah[mt][3],
                             bh[g][p], bh[g][p + 2]);
                    mma_bf16(cc[0], cc[1], cc[2], cc[3],
                             ah[mt][0], ah[mt][1], ah[mt][2], ah[mt][3],
                             bl[g][p], bl[g][p + 2]);
                    mma_bf16(cc[0], cc[1], cc[2], cc[3],
                             al[mt][0], al[mt][1], al[mt][2], al[mt][3],
                             bh[g][p], bh[g][p + 2]);
                }
            }
        }
        __syncthreads();
    }

    float* mids = reinterpret_cast<float*>(smem) + G2_MIDS / 4;
    float* w3s  = reinterpret_cast<float*>(smem) + G2_W3S / 4;
    const float* b2 = bias2 + (size_t)batch * G2_NR;
    {
        const float* w3g = W3 + (size_t)batch * (G2_NR * T_OUT);
        for (int i = t; i < G2_NR * T_OUT; i += 256) w3s[i] = w3g[i];

        const int rl = wm * 32 + (lane >> 2);
        const int cb = wn * 48 + (lane & 3) * 2;
        #pragma unroll
        for (int mt = 0; mt < 2; mt++) {
            #pragma unroll
            for (int half = 0; half < 2; half++) {
                const int r = rl + mt * 16 + half * 8;
                float* row = mids + r * G2_MSTR;
                #pragma unroll
                for (int nt = 0; nt < 6; nt++) {
                    const int ccol = cb + nt * 8;
                    if (ccol < G2_NR) {
                        float2 v;
                        v.x = fmaxf(acc[mt][nt][half * 2 + 0] + b2[ccol], 0.f);
                        v.y = fmaxf(acc[mt][nt][half * 2 + 1] + b2[ccol + 1], 0.f);
                        *reinterpret_cast<float2*>(row + ccol) = v;
                    }
                }
            }
        }
    }
    __syncthreads();

    {
        const int r  = t >> 1;
        const int c0 = (t & 1) * 5;
        const float* b3 = bias3 + (size_t)batch * T_OUT;
        float a[5];
        #pragma unroll
        for (int j = 0; j < 5; j++) a[j] = b3[c0 + j];
        const float* row = mids + r * G2_MSTR;
        for (int k = 0; k < G2_NR; k++) {
            float tv = row[k];
            #pragma unroll
            for (int j = 0; j < 5; j++)
                a[j] = fmaf(tv, w3s[k * T_OUT + c0 + j], a[j]);
        }
        float* dst = Out + (long long)batch * outBatch +
                     (size_t)(r0 + r) * T_OUT + c0;
        #pragma unroll
        for (int j = 0; j < 5; j++) dst[j] = a[j];
    }
}

// ---------------------------------------------------------------------------
// Fused gate + T1 kernel  -- unchanged from R6
// ---------------------------------------------------------------------------
__global__ __launch_bounds__(256)
void gate_t1_kernel(const float* __restrict__ EO,
                    const float* __restrict__ gw,
                    const int*   __restrict__ gm,
                    const float* __restrict__ tW1,
                    const float* __restrict__ tb1,
                    float* __restrict__ T1out)
{
    __shared__ float Gs[128 * F_CONN];
    __shared__ float W1s[F_CONN * 120];

    const int t  = threadIdx.x;
    const int n  = blockIdx.x;
    const int r0 = blockIdx.y * 128;

    float w[M_EXP];
    #pragma unroll
    for (int m = 0; m < M_EXP; m++)
        w[m] = gw[m * N_TASK + n] * (float)gm[m * N_TASK + n];

    for (int i = t; i < 128 * F_CONN; i += 256) {
        float acc = 0.f;
        #pragma unroll
        for (int m = 0; m < M_EXP; m++)
            acc = fmaf(w[m], EO[((size_t)m * B_ROWS + r0) * F_CONN + i], acc);
        Gs[i] = acc;
    }
    for (int i = t; i < F_CONN * 120; i += 256)
        W1s[i] = tW1[(size_t)n * F_CONN * 120 + i];
    __syncthreads();

    const int r  = t >> 1;
    const int h0 = (t & 1) * 60;
    float g[F_CONN];
    #pragma unroll
    for (int f = 0; f < F_CONN; f++) g[f] = Gs[r * F_CONN + f];

    unsigned long long a2[30];
    const float* b1 = tb1 + (size_t)n * 120 + h0;
    #pragma unroll
    for (int j = 0; j < 30; j++) a2[j] = pack2(b1[2 * j], b1[2 * j + 1]);
    #pragma unroll
    for (int f = 0; f < F_CONN; f++) {
        unsigned long long gv = dup2(g[f]);
        const unsigned long long* wrow =
            reinterpret_cast<const unsigned long long*>(W1s + f * 120 + h0);
        #pragma unroll
        for (int j = 0; j < 30; j++) fma2(a2[j], gv, wrow[j]);
    }
    float* dst = T1out + ((size_t)n * B_ROWS + r0 + r) * 120 + h0;
    #pragma unroll
    for (int j = 0; j < 30; j += 2) {
        float x0, x1, x2, x3;
        unpack2(a2[j], x0, x1);
        unpack2(a2[j + 1], x2, x3);
        float4 v;
        v.x = fmaxf(x0, 0.f); v.y = fmaxf(x1, 0.f);
        v.z = fmaxf(x2, 0.f); v.w = fmaxf(x3, 0.f);
        *reinterpret_cast<float4*>(dst + 2 * j) = v;
    }
}

// ---------------------------------------------------------------------------
// logits_loss[n] = sum_m log_sigmoid(gate_logits[m][n])
// ---------------------------------------------------------------------------
__global__ void logits_kernel(const float* __restrict__ gl, float* __restrict__ out)
{
    int n = blockIdx.x * blockDim.x + threadIdx.x;
    if (n >= N_TASK) return;
    float acc = 0.f;
    #pragma unroll
    for (int m = 0; m < M_EXP; m++) {
        float v = gl[m * N_TASK + n];
        float ls = (v > 0.f) ? (-log1pf(expf(-v))) : (v - log1pf(expf(v)));
        acc += ls;
    }
    out[n] = acc;
}

// ---------------------------------------------------------------------------
// kernel_launch
// ---------------------------------------------------------------------------
extern "C" void kernel_launch(void* const* d_in, const int* in_sizes, int n_in,
                              void* d_out, int out_size)
{
    const float* x   = (const float*)d_in[0];
    const float* eW1 = (const float*)d_in[2];
    const float* eb1 = (const float*)d_in[3];
    const float* eW2 = (const float*)d_in[4];
    const float* eb2 = (const float*)d_in[5];
    const float* eW3 = (const float*)d_in[6];
    const float* eb3 = (const float*)d_in[7];
    const float* gw  = (const float*)d_in[8];
    const float* gl  = (const float*)d_in[9];
    const int*   gm  = (const int*)  d_in[10];
    const float* tW1 = (const float*)d_in[11];
    const float* tb1 = (const float*)d_in[12];
    const float* tW2 = (const float*)d_in[13];
    const float* tb2 = (const float*)d_in[14];
    const float* tW3 = (const float*)d_in[15];
    const float* tb3 = (const float*)d_in[16];
    float* out = (float*)d_out;

    float *H1, *EO, *T1b;
    __nv_bfloat16 *xph, *xpl, *wph, *wpl, *w2h, *w2l, *tw2h, *tw2l;
    cudaGetSymbolAddress((void**)&H1,  g_H1);
    cudaGetSymbolAddress((void**)&EO,  g_EO);
    cudaGetSymbolAddress((void**)&T1b, g_T1);
    cudaGetSymbolAddress((void**)&xph, g_xph);
    cudaGetSymbolAddress((void**)&xpl, g_xpl);
    cudaGetSymbolAddress((void**)&wph, g_wph);
    cudaGetSymbolAddress((void**)&wpl, g_wpl);
    cudaGetSymbolAddress((void**)&w2h, g_w2h);
    cudaGetSymbolAddress((void**)&w2l, g_w2l);
    cudaGetSymbolAddress((void**)&tw2h, g_tw2h);
    cudaGetSymbolAddress((void**)&tw2l, g_tw2l);

    cudaFuncSetAttribute(e1_mma_kernel,
                         cudaFuncAttributeMaxDynamicSharedMemorySize, E1_SMEM);
    cudaFuncSetAttribute(mma_gemm_fused2_kernel,
                         cudaFuncAttributeMaxDynamicSharedMemorySize, G2_SMEM);

    const dim3 blk(256);
    const int rowTiles = B_ROWS / 128;   // 64

    // ---- packing / conversions ----
    {
        size_t nx = (size_t)E1_NC * B_ROWS * PK_COLS;
        pack_x_kernel<<<(unsigned)((nx + 255) / 256), 256>>>(x, xph, xpl);
        size_t nw = (size_t)M_EXP * E1_NC * 128 * PK_COLS;
        pack_w_kernel<<<(unsigned)((nw + 255) / 256), 256>>>(eW1, wph, wpl);
        size_t n2 = (size_t)M_EXP * 96 * 128;
        convert_w2_kernel<<<(unsigned)((n2 + 255) / 256), 256>>>(
            eW2, M_EXP, 120, 84, w2h, w2l);
        size_t n3 = (size_t)N_TASK * 96 * 128;
        convert_w2_kernel<<<(unsigned)((n3 + 255) / 256), 256>>>(
            tW2, N_TASK, 120, 84, tw2h, tw2l);
    }

    // ---- E1 (HMMA, bulk loads) -> H1 ----
    e1_mma_kernel<<<dim3(M_EXP, rowTiles), blk, E1_SMEM>>>(
        xph, xpl, wph, wpl, eb1, H1);

    // ---- E2+E3 fused: H1 -> EO ----
    mma_gemm_fused2_kernel<<<dim3(M_EXP, rowTiles), blk, G2_SMEM>>>(
        H1, (long long)B_ROWS * 120, w2h, w2l, eb2,
        eW3, eb3, EO, (long long)B_ROWS * T_OUT);

    // ---- gate + T1 fused: EO -> T1b ----
    gate_t1_kernel<<<dim3(N_TASK, rowTiles), blk>>>(
        EO, gw, gm, tW1, tb1, T1b);

    // ---- T2+T3 fused: T1b -> out ----
    mma_gemm_fused2_kernel<<<dim3(N_TASK, rowTiles), blk, G2_SMEM>>>(
        T1b, (long long)B_ROWS * 120, tw2h, tw2l, tb2,
        tW3, tb3, out, (long long)B_ROWS * T_OUT);

    // logits_loss -> out tail
    logits_kernel<<<1, 128>>>(gl, out + (long long)N_TASK * B_ROWS * T_OUT);
}